// round 7
// baseline (speedup 1.0000x reference)
#include <cuda_runtime.h>
#include <cuda_bf16.h>
#include <math.h>

// Problem constants
#define NT   1024          // tokens
#define ND   2048          // hidden dim
#define NE   32            // experts
#define NI   1408          // routed intermediate
#define NSI  2816          // shared intermediate
#define NG   8             // groups
#define EPG  4             // experts per group
#define NA   (NT * 4)      // total assignments (top_k = 4, exact)

// ---------------- device scratch (no allocation allowed) ----------------
__device__ unsigned g_xh [NT * ND / 2];    // x split hi (k-paired u32)
__device__ unsigned g_xl [NT * ND / 2];    // x split lo
__device__ unsigned g_hh [NA * NI / 2];    // routed H hi
__device__ unsigned g_hl [NA * NI / 2];    // routed H lo
__device__ unsigned g_hsh[NT * NSI / 2];   // shared H hi
__device__ unsigned g_hsl[NT * NSI / 2];   // shared H lo
__device__ unsigned g_sgh[(ND / 2) * NSI]; // sw_gate hi   [ND/2][NSI]
__device__ unsigned g_sgl[(ND / 2) * NSI];
__device__ unsigned g_suh[(ND / 2) * NSI]; // sw_up hi
__device__ unsigned g_sul[(ND / 2) * NSI];
__device__ unsigned g_sdh[(NSI / 2) * ND]; // sw_down hi   [NSI/2][ND]
__device__ unsigned g_sdl[(NSI / 2) * ND];
__device__ int   g_rowlist[NA];
__device__ float g_roww  [NA];
__device__ int   g_counts [NE];
__device__ int   g_offsets[NE];
__device__ int   g_cursor [NE];
__device__ int   g_tid4[NA];
__device__ float g_tw4 [NA];

// ---------------- bf16 split helpers ----------------
// v = hi + lo (bf16 each); pack two consecutive-k values into one u32 (low = even k).
__device__ __forceinline__ void split2(float v0, float v1, unsigned& h, unsigned& l) {
    unsigned hh;
    asm("cvt.rn.bf16x2.f32 %0, %1, %2;" : "=r"(hh) : "f"(v1), "f"(v0));
    float h0 = __uint_as_float(hh << 16);
    float h1 = __uint_as_float(hh & 0xffff0000u);
    asm("cvt.rn.bf16x2.f32 %0, %1, %2;" : "=r"(l) : "f"(v1 - h1), "f"(v0 - h0));
    h = hh;
}

// D += A(16x16 bf16) * B(16x8 bf16), fp32 accumulate
__device__ __forceinline__ void mma_bf16(float* d, const unsigned* a, const unsigned* b) {
    asm volatile(
        "mma.sync.aligned.m16n8k16.row.col.f32.bf16.bf16.f32 "
        "{%0,%1,%2,%3}, {%4,%5,%6,%7}, {%8,%9}, {%0,%1,%2,%3};"
        : "+f"(d[0]), "+f"(d[1]), "+f"(d[2]), "+f"(d[3])
        : "r"(a[0]), "r"(a[1]), "r"(a[2]), "r"(a[3]), "r"(b[0]), "r"(b[1]));
}

// ---------------- prologue split kernels ----------------
__global__ void split_x_kernel(const float* __restrict__ x) {
    int idx = blockIdx.x * 256 + threadIdx.x;            // NT*ND/4 threads
    int row = idx / (ND / 4), c4 = idx % (ND / 4);
    float4 v = *(const float4*)(x + (size_t)row * ND + c4 * 4);
    unsigned h0, l0, h1, l1;
    split2(v.x, v.y, h0, l0);
    split2(v.z, v.w, h1, l1);
    size_t o = (size_t)row * (ND / 2) + c4 * 2;
    g_xh[o] = h0; g_xh[o + 1] = h1;
    g_xl[o] = l0; g_xl[o + 1] = l1;
}

// W [K][N] fp32 -> WH/WL [K/2][N] u32 (pair rows 2kp, 2kp+1)
__global__ void split_w_kernel(const float* __restrict__ W,
                               unsigned* __restrict__ WH,
                               unsigned* __restrict__ WL, int K, int N) {
    int idx = blockIdx.x * 256 + threadIdx.x;            // (K/2)*(N/4) threads
    int kp = idx / (N / 4), c4 = idx % (N / 4);
    const float* p0 = W + (size_t)(2 * kp) * N + c4 * 4;
    float4 r0 = *(const float4*)p0;
    float4 r1 = *(const float4*)(p0 + N);
    uint4 h, l;
    split2(r0.x, r1.x, h.x, l.x);
    split2(r0.y, r1.y, h.y, l.y);
    split2(r0.z, r1.z, h.z, l.z);
    split2(r0.w, r1.w, h.w, l.w);
    size_t o = (size_t)kp * N + c4 * 4;
    *(uint4*)(WH + o) = h;
    *(uint4*)(WL + o) = l;
}

// ---------------- tiny kernels ----------------
__global__ void zero_kernel() {
    int i = threadIdx.x;
    if (i < NE) { g_counts[i] = 0; g_cursor[i] = 0; }
}

// One block per token: logits = x@gate_w^T + gate_b ; sigmoid ; biased grouped top-k.
__global__ void gate_kernel(const float* __restrict__ x,
                            const float* __restrict__ gw,
                            const float* __restrict__ gb) {
    __shared__ float xs[ND];
    __shared__ float logit[NE];
    int t = blockIdx.x;
    for (int k = threadIdx.x; k < ND; k += 256) xs[k] = x[(size_t)t * ND + k];
    __syncthreads();

    int e = threadIdx.x >> 3;
    int j = threadIdx.x & 7;
    const float* w = gw + (size_t)e * ND;
    float s = 0.f;
    for (int k = j; k < ND; k += 8) s += xs[k] * w[k];
    s += __shfl_xor_sync(0xffffffffu, s, 1);
    s += __shfl_xor_sync(0xffffffffu, s, 2);
    s += __shfl_xor_sync(0xffffffffu, s, 4);
    if (j == 0) logit[e] = s + gb[e];
    __syncthreads();

    if (threadIdx.x == 0) {
        float sc[NE], scb[NE];
        #pragma unroll
        for (int i = 0; i < NE; i++) {
            float v = 1.f / (1.f + expf(-logit[i]));
            sc[i]  = v;
            scb[i] = v + gb[i];
        }
        float gs[NG];
        #pragma unroll
        for (int g = 0; g < NG; g++) {
            float m1 = -1e30f, m2 = -1e30f;
            #pragma unroll
            for (int q = 0; q < EPG; q++) {
                float v = scb[g * EPG + q];
                if (v > m1) { m2 = m1; m1 = v; } else if (v > m2) { m2 = v; }
            }
            gs[g] = m1 + m2;
        }
        bool gsel[NG];
        #pragma unroll
        for (int g = 0; g < NG; g++) gsel[g] = false;
        for (int r = 0; r < 4; r++) {
            float best = -1e30f; int bi = 0;
            for (int g = 0; g < NG; g++)
                if (!gsel[g] && gs[g] > best) { best = gs[g]; bi = g; }
            gsel[bi] = true;
        }
        float tmp[NE];
        #pragma unroll
        for (int i = 0; i < NE; i++) tmp[i] = gsel[i / EPG] ? scb[i] : 0.0f;
        int ids[4]; float tw[4]; float wsum = 0.f;
        for (int r = 0; r < 4; r++) {
            float best = -1e30f; int bi = 0;
            for (int i = 0; i < NE; i++)
                if (tmp[i] > best) { best = tmp[i]; bi = i; }
            tmp[bi] = -1e30f;
            ids[r] = bi;
            tw[r] = sc[bi];
            wsum += tw[r];
        }
        float inv = 1.f / wsum;
        for (int r = 0; r < 4; r++) {
            g_tid4[t * 4 + r] = ids[r];
            g_tw4 [t * 4 + r] = tw[r] * inv;
            atomicAdd(&g_counts[ids[r]], 1);
        }
    }
}

__global__ void scan_kernel() {
    int tid = threadIdx.x;
    int c = g_counts[tid];
    int v = c;
    #pragma unroll
    for (int o = 1; o < 32; o <<= 1) {
        int u = __shfl_up_sync(0xffffffffu, v, o);
        if (tid >= o) v += u;
    }
    g_offsets[tid] = v - c;
}

__global__ void scatter_kernel() {
    int i = blockIdx.x * blockDim.x + threadIdx.x;
    if (i >= NA) return;
    int t = i >> 2;
    int e = g_tid4[i];
    int pos = atomicAdd(&g_cursor[e], 1);
    int row = g_offsets[e] + pos;
    g_rowlist[row] = t;
    g_roww[row]   = g_tw4[i];
}

// ============================================================================
// bf16x3 tensor-core GEMMs. A side always pre-split (g_xh/g_xl or g_hh/g_hl).
// B side: PRE_B -> pre-split arrays; else inline split of fp32 weights.
// Block BM=128, BN=64, BK=16 (8 u32 k-pairs), 256 threads = 8 warps (4M x 2N),
// warp tile 32x32. A SMEM [128][8] u32 XOR-swizzled (c ^ (row&7));
// B SMEM [8][72] u32 (stride 72 == 8 mod 32).
// ============================================================================

#define B_STR 72

// ---------------- GEMM 1: H = silu(A@Wg) * (A@Wu) ----------------
template<int IDIM, bool GATHER, bool PRE_B>
__global__ void __launch_bounds__(256, 2)
gemm_gated(const float* __restrict__ Wg,  const float* __restrict__ Wu,
           const unsigned* __restrict__ BGH, const unsigned* __restrict__ BGL,
           const unsigned* __restrict__ BUH, const unsigned* __restrict__ BUL,
           unsigned* __restrict__ HH, unsigned* __restrict__ HL) {
    int e   = GATHER ? blockIdx.z : 0;
    int cnt = GATHER ? g_counts[e]  : NT;
    int off = GATHER ? g_offsets[e] : 0;
    int m0  = blockIdx.x * 128;
    if (m0 >= cnt) return;
    int n0  = blockIdx.y * 64;

    __shared__ unsigned Ah[128 * 8], Al[128 * 8];
    __shared__ unsigned Bgh[8 * B_STR], Bgl[8 * B_STR];
    __shared__ unsigned Buh[8 * B_STR], Bul[8 * B_STR];

    int tid  = threadIdx.x;
    int lane = tid & 31, wid = tid >> 5;
    int warpM = wid >> 1, warpN = wid & 1;
    int gq = lane >> 2, tq = lane & 3;

    // A loader: one uint4 per thread per array (128 rows x 8 u32)
    int arow = tid >> 1, acb = (tid & 1) << 2;
    int am = m0 + arow;
    int tok;
    if (GATHER) tok = (am < cnt) ? g_rowlist[off + am] : 0;
    else        tok = (am < cnt) ? am : 0;
    const unsigned* ahp = g_xh + (size_t)tok * (ND / 2) + acb;
    const unsigned* alp = g_xl + (size_t)tok * (ND / 2) + acb;

    // B loader
    int mat = tid >> 7;
    int rr  = tid & 127;
    int kpw = rr >> 4;
    int nq  = (rr & 15) << 2;
    const float*    bp  = nullptr;
    const unsigned* bhp = nullptr;
    const unsigned* blp = nullptr;
    if (PRE_B) {
        bhp = (mat ? BUH : BGH) + (size_t)kpw * IDIM + n0 + nq;
        blp = (mat ? BUL : BGL) + (size_t)kpw * IDIM + n0 + nq;
    } else {
        const float* wsel = (mat ? Wu : Wg) + (size_t)e * ND * IDIM;
        bp = wsel + (size_t)(2 * kpw) * IDIM + n0 + nq;
    }
    unsigned* BHs = mat ? Buh : Bgh;
    unsigned* BLs = mat ? Bul : Bgl;

    float accg[2][4][4], accu[2][4][4];
    #pragma unroll
    for (int mt = 0; mt < 2; mt++)
        #pragma unroll
        for (int nt = 0; nt < 4; nt++)
            #pragma unroll
            for (int r = 0; r < 4; r++) { accg[mt][nt][r] = 0.f; accu[mt][nt][r] = 0.f; }

    uint4 rah = *(const uint4*)ahp;
    uint4 ral = *(const uint4*)alp;
    float4 rb0, rb1;
    uint4 rbh, rbl;
    if (PRE_B) { rbh = *(const uint4*)bhp; rbl = *(const uint4*)blp; }
    else       { rb0 = *(const float4*)bp; rb1 = *(const float4*)(bp + IDIM); }

    for (int kt = 0; kt < ND; kt += 16) {
        // ---- store A (pre-split, swizzled) ----
        {
            int s = arow & 7, base = arow * 8;
            Ah[base + ((acb + 0) ^ s)] = rah.x;
            Ah[base + ((acb + 1) ^ s)] = rah.y;
            Ah[base + ((acb + 2) ^ s)] = rah.z;
            Ah[base + ((acb + 3) ^ s)] = rah.w;
            Al[base + ((acb + 0) ^ s)] = ral.x;
            Al[base + ((acb + 1) ^ s)] = ral.y;
            Al[base + ((acb + 2) ^ s)] = ral.z;
            Al[base + ((acb + 3) ^ s)] = ral.w;
        }
        // ---- store B ----
        if (PRE_B) {
            *(uint4*)&BHs[kpw * B_STR + nq] = rbh;
            *(uint4*)&BLs[kpw * B_STR + nq] = rbl;
        } else {
            uint4 h, l;
            split2(rb0.x, rb1.x, h.x, l.x);
            split2(rb0.y, rb1.y, h.y, l.y);
            split2(rb0.z, rb1.z, h.z, l.z);
            split2(rb0.w, rb1.w, h.w, l.w);
            *(uint4*)&BHs[kpw * B_STR + nq] = h;
            *(uint4*)&BLs[kpw * B_STR + nq] = l;
        }
        __syncthreads();
        if (kt + 16 < ND) {
            rah = *(const uint4*)(ahp + (kt + 16) / 2);
            ral = *(const uint4*)(alp + (kt + 16) / 2);
            if (PRE_B) {
                rbh = *(const uint4*)(bhp + (size_t)((kt + 16) / 2) * IDIM);
                rbl = *(const uint4*)(blp + (size_t)((kt + 16) / 2) * IDIM);
            } else {
                rb0 = *(const float4*)(bp + (size_t)(kt + 16) * IDIM);
                rb1 = *(const float4*)(bp + (size_t)(kt + 17) * IDIM);
            }
        }
        // ---- fragments + mma ----
        {
            unsigned ah[2][4], al[2][4];
            #pragma unroll
            for (int mt = 0; mt < 2; mt++) {
                int R = warpM * 32 + mt * 16 + gq;
                int base = R * 8;
                int c0 = tq ^ gq, c1 = (tq + 4) ^ gq;
                ah[mt][0] = Ah[base + c0];
                ah[mt][1] = Ah[base + 64 + c0];
                ah[mt][2] = Ah[base + c1];
                ah[mt][3] = Ah[base + 64 + c1];
                al[mt][0] = Al[base + c0];
                al[mt][1] = Al[base + 64 + c0];
                al[mt][2] = Al[base + c1];
                al[mt][3] = Al[base + 64 + c1];
            }
            #pragma unroll
            for (int nt = 0; nt < 4; nt++) {
                int c = warpN * 32 + nt * 8 + gq;
                unsigned bgh[2], bgl[2], buh[2], bul[2];
                bgh[0] = Bgh[tq * B_STR + c]; bgh[1] = Bgh[(tq + 4) * B_STR + c];
                bgl[0] = Bgl[tq * B_STR + c]; bgl[1] = Bgl[(tq + 4) * B_STR + c];
                buh[0] = Buh[tq * B_STR + c]; buh[1] = Buh[(tq + 4) * B_STR + c];
                bul[0] = Bul[tq * B_STR + c]; bul[1] = Bul[(tq + 4) * B_STR + c];
                #pragma unroll
                for (int mt = 0; mt < 2; mt++) {
                    mma_bf16(accg[mt][nt], ah[mt], bgh);
                    mma_bf16(accg[mt][nt], al[mt], bgh);
                    mma_bf16(accg[mt][nt], ah[mt], bgl);
                    mma_bf16(accu[mt][nt], ah[mt], buh);
                    mma_bf16(accu[mt][nt], al[mt], buh);
                    mma_bf16(accu[mt][nt], ah[mt], bul);
                }
            }
        }
        __syncthreads();
    }
    // epilogue: silu(gate)*up, split to hi/lo, store packed u32
    #pragma unroll
    for (int mt = 0; mt < 2; mt++) {
        #pragma unroll
        for (int half = 0; half < 2; half++) {
            int r = m0 + warpM * 32 + mt * 16 + half * 8 + gq;
            if (r >= cnt) continue;
            size_t rowo = (size_t)(off + r) * (IDIM / 2);
            #pragma unroll
            for (int nt = 0; nt < 4; nt++) {
                float gv0 = accg[mt][nt][half * 2 + 0];
                float gv1 = accg[mt][nt][half * 2 + 1];
                float uv0 = accu[mt][nt][half * 2 + 0];
                float uv1 = accu[mt][nt][half * 2 + 1];
                float h0 = gv0 / (1.f + expf(-gv0)) * uv0;
                float h1 = gv1 / (1.f + expf(-gv1)) * uv1;
                unsigned hh_, hl_;
                split2(h0, h1, hh_, hl_);
                int hcol = (n0 >> 1) + warpN * 16 + nt * 4 + tq;
                HH[rowo + hcol] = hh_;
                HL[rowo + hcol] = hl_;
            }
        }
    }
}

// ---------------- GEMM 2: out (+)= H @ Wd ----------------
template<int IDIM, bool ROUTED, bool PRE_B>
__global__ void __launch_bounds__(256, 2)
gemm_down(const unsigned* __restrict__ AH, const unsigned* __restrict__ AL,
          const float* __restrict__ Wd,
          const unsigned* __restrict__ BHp, const unsigned* __restrict__ BLp,
          float* __restrict__ out) {
    int e   = ROUTED ? blockIdx.z : 0;
    int cnt = ROUTED ? g_counts[e]  : NT;
    int off = ROUTED ? g_offsets[e] : 0;
    int m0  = blockIdx.x * 128;
    if (m0 >= cnt) return;
    int n0  = blockIdx.y * 64;

    __shared__ unsigned Ah[128 * 8], Al[128 * 8];
    __shared__ unsigned Bh[8 * B_STR], Bl[8 * B_STR];

    int tid  = threadIdx.x;
    int lane = tid & 31, wid = tid >> 5;
    int warpM = wid >> 1, warpN = wid & 1;
    int gq = lane >> 2, tq = lane & 3;

    // A loader: pre-split H rows (stride IDIM/2 u32)
    int arow = tid >> 1, acb = (tid & 1) << 2;
    int am = m0 + arow;
    int hr = (am < cnt) ? (off + am) : off;
    const unsigned* ahp = AH + (size_t)hr * (IDIM / 2) + acb;
    const unsigned* alp = AL + (size_t)hr * (IDIM / 2) + acb;

    // B loader: first 128 threads
    int bact = (tid < 128);
    int kpw = (tid & 127) >> 4;
    int nq  = (tid & 15) << 2;
    const float*    bp  = nullptr;
    const unsigned* bhp = nullptr;
    const unsigned* blp = nullptr;
    if (PRE_B) {
        bhp = BHp + (size_t)kpw * ND + n0 + nq;
        blp = BLp + (size_t)kpw * ND + n0 + nq;
    } else {
        const float* wd = Wd + (size_t)e * IDIM * ND;
        bp = wd + (size_t)(2 * kpw) * ND + n0 + nq;
    }

    float acc[2][4][4];
    #pragma unroll
    for (int mt = 0; mt < 2; mt++)
        #pragma unroll
        for (int nt = 0; nt < 4; nt++)
            #pragma unroll
            for (int r = 0; r < 4; r++) acc[mt][nt][r] = 0.f;

    uint4 rah = *(const uint4*)ahp;
    uint4 ral = *(const uint4*)alp;
    float4 rb0, rb1;
    uint4 rbh, rbl;
    if (bact) {
        if (PRE_B) { rbh = *(const uint4*)bhp; rbl = *(const uint4*)blp; }
        else       { rb0 = *(const float4*)bp; rb1 = *(const float4*)(bp + ND); }
    }

    for (int kt = 0; kt < IDIM; kt += 16) {
        {
            int s = arow & 7, base = arow * 8;
            Ah[base + ((acb + 0) ^ s)] = rah.x;
            Ah[base + ((acb + 1) ^ s)] = rah.y;
            Ah[base + ((acb + 2) ^ s)] = rah.z;
            Ah[base + ((acb + 3) ^ s)] = rah.w;
            Al[base + ((acb + 0) ^ s)] = ral.x;
            Al[base + ((acb + 1) ^ s)] = ral.y;
            Al[base + ((acb + 2) ^ s)] = ral.z;
            Al[base + ((acb + 3) ^ s)] = ral.w;
        }
        if (bact) {
            if (PRE_B) {
                *(uint4*)&Bh[kpw * B_STR + nq] = rbh;
                *(uint4*)&Bl[kpw * B_STR + nq] = rbl;
            } else {
                uint4 h, l;
                split2(rb0.x, rb1.x, h.x, l.x);
                split2(rb0.y, rb1.y, h.y, l.y);
                split2(rb0.z, rb1.z, h.z, l.z);
                split2(rb0.w, rb1.w, h.w, l.w);
                *(uint4*)&Bh[kpw * B_STR + nq] = h;
                *(uint4*)&Bl[kpw * B_STR + nq] = l;
            }
        }
        __syncthreads();
        if (kt + 16 < IDIM) {
            rah = *(const uint4*)(ahp + (kt + 16) / 2);
            ral = *(const uint4*)(alp + (kt + 16) / 2);
            if (bact) {
                if (PRE_B) {
                    rbh = *(const uint4*)(bhp + (size_t)((kt + 16) / 2) * ND);
                    rbl = *(const uint4*)(blp + (size_t)((kt + 16) / 2) * ND);
                } else {
                    rb0 = *(const float4*)(bp + (size_t)(kt + 16) * ND);
                    rb1 = *(const float4*)(bp + (size_t)(kt + 17) * ND);
                }
            }
        }
        {
            unsigned ah[2][4], al[2][4];
            #pragma unroll
            for (int mt = 0; mt < 2; mt++) {
                int R = warpM * 32 + mt * 16 + gq;
                int base = R * 8;
                int c0 = tq ^ gq, c1 = (tq + 4) ^ gq;
                ah[mt][0] = Ah[base + c0];
                ah[mt][1] = Ah[base + 64 + c0];
                ah[mt][2] = Ah[base + c1];
                ah[mt][3] = Ah[base + 64 + c1];
                al[mt][0] = Al[base + c0];
                al[mt][1] = Al[base + 64 + c0];
                al[mt][2] = Al[base + c1];
                al[mt][3] = Al[base + 64 + c1];
            }
            #pragma unroll
            for (int nt = 0; nt < 4; nt++) {
                int c = warpN * 32 + nt * 8 + gq;
                unsigned bh[2], bl[2];
                bh[0] = Bh[tq * B_STR + c]; bh[1] = Bh[(tq + 4) * B_STR + c];
                bl[0] = Bl[tq * B_STR + c]; bl[1] = Bl[(tq + 4) * B_STR + c];
                #pragma unroll
                for (int mt = 0; mt < 2; mt++) {
                    mma_bf16(acc[mt][nt], ah[mt], bh);
                    mma_bf16(acc[mt][nt], al[mt], bh);
                    mma_bf16(acc[mt][nt], ah[mt], bl);
                }
            }
        }
        __syncthreads();
    }
    // epilogue
    #pragma unroll
    for (int mt = 0; mt < 2; mt++) {
        #pragma unroll
        for (int half = 0; half < 2; half++) {
            int r = m0 + warpM * 32 + mt * 16 + half * 8 + gq;
            if (r >= cnt) continue;
            if (ROUTED) {
                int grow = off + r;
                int tok  = g_rowlist[grow];
                float w  = g_roww[grow] * 2.5f;
                float* op = out + (size_t)tok * ND + n0 + warpN * 32;
                #pragma unroll
                for (int nt = 0; nt < 4; nt++) {
                    atomicAdd(&op[nt * 8 + 2 * tq],     w * acc[mt][nt][half * 2 + 0]);
                    atomicAdd(&op[nt * 8 + 2 * tq + 1], w * acc[mt][nt][half * 2 + 1]);
                }
            } else {
                float* op = out + (size_t)r * ND + n0 + warpN * 32;
                #pragma unroll
                for (int nt = 0; nt < 4; nt++) {
                    float2 v;
                    v.x = acc[mt][nt][half * 2 + 0];
                    v.y = acc[mt][nt][half * 2 + 1];
                    *(float2*)&op[nt * 8 + 2 * tq] = v;
                }
            }
        }
    }
}

// ---------------- launch ----------------
extern "C" void kernel_launch(void* const* d_in, const int* in_sizes, int n_in,
                              void* d_out, int out_size) {
    const float* x       = (const float*)d_in[0];
    const float* gate_w  = (const float*)d_in[1];
    const float* gate_b  = (const float*)d_in[2];
    const float* w_gate  = (const float*)d_in[3];
    const float* w_up    = (const float*)d_in[4];
    const float* w_down  = (const float*)d_in[5];
    const float* sw_gate = (const float*)d_in[6];
    const float* sw_up   = (const float*)d_in[7];
    const float* sw_down = (const float*)d_in[8];
    float* out = (float*)d_out;

    unsigned *xh, *xl, *hh, *hl, *hsh, *hsl, *sgh, *sgl, *suh, *sul, *sdh, *sdl;
    cudaGetSymbolAddress((void**)&xh,  g_xh);
    cudaGetSymbolAddress((void**)&xl,  g_xl);
    cudaGetSymbolAddress((void**)&hh,  g_hh);
    cudaGetSymbolAddress((void**)&hl,  g_hl);
    cudaGetSymbolAddress((void**)&hsh, g_hsh);
    cudaGetSymbolAddress((void**)&hsl, g_hsl);
    cudaGetSymbolAddress((void**)&sgh, g_sgh);
    cudaGetSymbolAddress((void**)&sgl, g_sgl);
    cudaGetSymbolAddress((void**)&suh, g_suh);
    cudaGetSymbolAddress((void**)&sul, g_sul);
    cudaGetSymbolAddress((void**)&sdh, g_sdh);
    cudaGetSymbolAddress((void**)&sdl, g_sdl);

    zero_kernel   <<<1, 32>>>();
    gate_kernel   <<<NT, 256>>>(x, gate_w, gate_b);
    scan_kernel   <<<1, 32>>>();
    scatter_kernel<<<NA / 256, 256>>>();

    // prologue splits
    split_x_kernel<<<(NT * ND / 4) / 256, 256>>>(x);
    split_w_kernel<<<((ND / 2) * (NSI / 4)) / 256, 256>>>(sw_gate, sgh, sgl, ND, NSI);
    split_w_kernel<<<((ND / 2) * (NSI / 4)) / 256, 256>>>(sw_up,   suh, sul, ND, NSI);
    split_w_kernel<<<((NSI / 2) * (ND / 4)) / 256, 256>>>(sw_down, sdh, sdl, NSI, ND);

    // shared expert gate/up (pre-split B)
    gemm_gated<NSI, false, true><<<dim3(NT / 128, NSI / 64, 1), 256>>>(
        nullptr, nullptr, sgh, sgl, suh, sul, hsh, hsl);
    // routed experts gate/up (inline B split)
    gemm_gated<NI, true, false><<<dim3(NT / 128, NI / 64, NE), 256>>>(
        w_gate, w_up, nullptr, nullptr, nullptr, nullptr, hh, hl);
    // shared down-proj: plain stores initialize out
    gemm_down<NSI, false, true><<<dim3(NT / 128, ND / 64, 1), 256>>>(
        hsh, hsl, nullptr, sdh, sdl, out);
    // routed down-proj: weighted atomic accumulation
    gemm_down<NI, true, false><<<dim3(NT / 128, ND / 64, NE), 256>>>(
        hh, hl, w_down, nullptr, nullptr, out);
}

// round 8
// speedup vs baseline: 1.0031x; 1.0031x over previous
#include <cuda_runtime.h>
#include <cuda_bf16.h>
#include <math.h>

// Problem constants
#define NT   1024          // tokens
#define ND   2048          // hidden dim
#define NE   32            // experts
#define NI   1408          // routed intermediate
#define NSI  2816          // shared intermediate
#define NG   8             // groups
#define EPG  4             // experts per group
#define NA   (NT * 4)      // total assignments (top_k = 4, exact)

// ---------------- device scratch (no allocation allowed) ----------------
__device__ unsigned g_xh [NT * ND / 2];    // x split hi (k-paired u32)
__device__ unsigned g_xl [NT * ND / 2];    // x split lo
__device__ unsigned g_hh [NA * NI / 2];    // routed H hi
__device__ unsigned g_hl [NA * NI / 2];    // routed H lo
__device__ unsigned g_hsh[NT * NSI / 2];   // shared H hi
__device__ unsigned g_hsl[NT * NSI / 2];   // shared H lo
__device__ unsigned g_sgh[(ND / 2) * NSI]; // sw_gate hi   [ND/2][NSI]
__device__ unsigned g_sgl[(ND / 2) * NSI];
__device__ unsigned g_suh[(ND / 2) * NSI]; // sw_up hi
__device__ unsigned g_sul[(ND / 2) * NSI];
__device__ unsigned g_sdh[(NSI / 2) * ND]; // sw_down hi   [NSI/2][ND]
__device__ unsigned g_sdl[(NSI / 2) * ND];
__device__ int   g_rowlist[NA];
__device__ float g_roww  [NA];
__device__ int   g_counts [NE];
__device__ int   g_offsets[NE];
__device__ int   g_cursor [NE];
__device__ int   g_tid4[NA];
__device__ float g_tw4 [NA];

// ---------------- bf16 split helpers ----------------
// v = hi + lo (bf16 each); pack two consecutive-k values into one u32 (low = even k).
__device__ __forceinline__ void split2(float v0, float v1, unsigned& h, unsigned& l) {
    unsigned hh;
    asm("cvt.rn.bf16x2.f32 %0, %1, %2;" : "=r"(hh) : "f"(v1), "f"(v0));
    float h0 = __uint_as_float(hh << 16);
    float h1 = __uint_as_float(hh & 0xffff0000u);
    asm("cvt.rn.bf16x2.f32 %0, %1, %2;" : "=r"(l) : "f"(v1 - h1), "f"(v0 - h0));
    h = hh;
}

// D += A(16x16 bf16) * B(16x8 bf16), fp32 accumulate
__device__ __forceinline__ void mma_bf16(float* d, const unsigned* a, const unsigned* b) {
    asm volatile(
        "mma.sync.aligned.m16n8k16.row.col.f32.bf16.bf16.f32 "
        "{%0,%1,%2,%3}, {%4,%5,%6,%7}, {%8,%9}, {%0,%1,%2,%3};"
        : "+f"(d[0]), "+f"(d[1]), "+f"(d[2]), "+f"(d[3])
        : "r"(a[0]), "r"(a[1]), "r"(a[2]), "r"(a[3]), "r"(b[0]), "r"(b[1]));
}

// ---------------- prologue split kernels ----------------
__global__ void split_x_kernel(const float* __restrict__ x) {
    int idx = blockIdx.x * 256 + threadIdx.x;            // NT*ND/4 threads
    int row = idx / (ND / 4), c4 = idx % (ND / 4);
    float4 v = *(const float4*)(x + (size_t)row * ND + c4 * 4);
    unsigned h0, l0, h1, l1;
    split2(v.x, v.y, h0, l0);
    split2(v.z, v.w, h1, l1);
    size_t o = (size_t)row * (ND / 2) + c4 * 2;
    g_xh[o] = h0; g_xh[o + 1] = h1;
    g_xl[o] = l0; g_xl[o + 1] = l1;
}

// W [K][N] fp32 -> WH/WL [K/2][N] u32 (pair rows 2kp, 2kp+1)
__global__ void split_w_kernel(const float* __restrict__ W,
                               unsigned* __restrict__ WH,
                               unsigned* __restrict__ WL, int K, int N) {
    int idx = blockIdx.x * 256 + threadIdx.x;            // (K/2)*(N/4) threads
    int kp = idx / (N / 4), c4 = idx % (N / 4);
    const float* p0 = W + (size_t)(2 * kp) * N + c4 * 4;
    float4 r0 = *(const float4*)p0;
    float4 r1 = *(const float4*)(p0 + N);
    uint4 h, l;
    split2(r0.x, r1.x, h.x, l.x);
    split2(r0.y, r1.y, h.y, l.y);
    split2(r0.z, r1.z, h.z, l.z);
    split2(r0.w, r1.w, h.w, l.w);
    size_t o = (size_t)kp * N + c4 * 4;
    *(uint4*)(WH + o) = h;
    *(uint4*)(WL + o) = l;
}

// ---------------- tiny kernels ----------------
__global__ void zero_kernel() {
    int i = threadIdx.x;
    if (i < NE) { g_counts[i] = 0; g_cursor[i] = 0; }
}

// One block per token: logits = x@gate_w^T + gate_b ; sigmoid ; biased grouped top-k.
__global__ void gate_kernel(const float* __restrict__ x,
                            const float* __restrict__ gw,
                            const float* __restrict__ gb) {
    __shared__ float xs[ND];
    __shared__ float logit[NE];
    int t = blockIdx.x;
    for (int k = threadIdx.x; k < ND; k += 256) xs[k] = x[(size_t)t * ND + k];
    __syncthreads();

    int e = threadIdx.x >> 3;
    int j = threadIdx.x & 7;
    const float* w = gw + (size_t)e * ND;
    float s = 0.f;
    for (int k = j; k < ND; k += 8) s += xs[k] * w[k];
    s += __shfl_xor_sync(0xffffffffu, s, 1);
    s += __shfl_xor_sync(0xffffffffu, s, 2);
    s += __shfl_xor_sync(0xffffffffu, s, 4);
    if (j == 0) logit[e] = s + gb[e];
    __syncthreads();

    if (threadIdx.x == 0) {
        float sc[NE], scb[NE];
        #pragma unroll
        for (int i = 0; i < NE; i++) {
            float v = 1.f / (1.f + expf(-logit[i]));
            sc[i]  = v;
            scb[i] = v + gb[i];
        }
        float gs[NG];
        #pragma unroll
        for (int g = 0; g < NG; g++) {
            float m1 = -1e30f, m2 = -1e30f;
            #pragma unroll
            for (int q = 0; q < EPG; q++) {
                float v = scb[g * EPG + q];
                if (v > m1) { m2 = m1; m1 = v; } else if (v > m2) { m2 = v; }
            }
            gs[g] = m1 + m2;
        }
        bool gsel[NG];
        #pragma unroll
        for (int g = 0; g < NG; g++) gsel[g] = false;
        for (int r = 0; r < 4; r++) {
            float best = -1e30f; int bi = 0;
            for (int g = 0; g < NG; g++)
                if (!gsel[g] && gs[g] > best) { best = gs[g]; bi = g; }
            gsel[bi] = true;
        }
        float tmp[NE];
        #pragma unroll
        for (int i = 0; i < NE; i++) tmp[i] = gsel[i / EPG] ? scb[i] : 0.0f;
        int ids[4]; float tw[4]; float wsum = 0.f;
        for (int r = 0; r < 4; r++) {
            float best = -1e30f; int bi = 0;
            for (int i = 0; i < NE; i++)
                if (tmp[i] > best) { best = tmp[i]; bi = i; }
            tmp[bi] = -1e30f;
            ids[r] = bi;
            tw[r] = sc[bi];
            wsum += tw[r];
        }
        float inv = 1.f / wsum;
        for (int r = 0; r < 4; r++) {
            g_tid4[t * 4 + r] = ids[r];
            g_tw4 [t * 4 + r] = tw[r] * inv;
            atomicAdd(&g_counts[ids[r]], 1);
        }
    }
}

__global__ void scan_kernel() {
    int tid = threadIdx.x;
    int c = g_counts[tid];
    int v = c;
    #pragma unroll
    for (int o = 1; o < 32; o <<= 1) {
        int u = __shfl_up_sync(0xffffffffu, v, o);
        if (tid >= o) v += u;
    }
    g_offsets[tid] = v - c;
}

__global__ void scatter_kernel() {
    int i = blockIdx.x * blockDim.x + threadIdx.x;
    if (i >= NA) return;
    int t = i >> 2;
    int e = g_tid4[i];
    int pos = atomicAdd(&g_cursor[e], 1);
    int row = g_offsets[e] + pos;
    g_rowlist[row] = t;
    g_roww[row]   = g_tw4[i];
}

// ============================================================================
// bf16x3 tensor-core GEMMs. A side always pre-split (g_xh/g_xl or g_hh/g_hl).
// B side: PRE_B -> pre-split arrays; else inline split of fp32 weights.
// Block BM=128, BN=64, BK=16 (8 u32 k-pairs), 256 threads = 8 warps (4M x 2N),
// warp tile 32x32. A SMEM [128][8] u32 XOR-swizzled (c ^ (row&7));
// B SMEM [8][72] u32 (stride 72 == 8 mod 32).
// ============================================================================

#define B_STR 72

// ---------------- GEMM 1: H = silu(A@Wg) * (A@Wu) ----------------
template<int IDIM, bool GATHER, bool PRE_B>
__global__ void __launch_bounds__(256, 2)
gemm_gated(const float* __restrict__ Wg,  const float* __restrict__ Wu,
           const unsigned* __restrict__ BGH, const unsigned* __restrict__ BGL,
           const unsigned* __restrict__ BUH, const unsigned* __restrict__ BUL,
           unsigned* __restrict__ HH, unsigned* __restrict__ HL) {
    int e   = GATHER ? blockIdx.z : 0;
    int cnt = GATHER ? g_counts[e]  : NT;
    int off = GATHER ? g_offsets[e] : 0;
    int m0  = blockIdx.x * 128;
    if (m0 >= cnt) return;
    int n0  = blockIdx.y * 64;

    __shared__ unsigned Ah[128 * 8], Al[128 * 8];
    __shared__ unsigned Bgh[8 * B_STR], Bgl[8 * B_STR];
    __shared__ unsigned Buh[8 * B_STR], Bul[8 * B_STR];

    int tid  = threadIdx.x;
    int lane = tid & 31, wid = tid >> 5;
    int warpM = wid >> 1, warpN = wid & 1;
    int gq = lane >> 2, tq = lane & 3;

    // A loader: one uint4 per thread per array (128 rows x 8 u32)
    int arow = tid >> 1, acb = (tid & 1) << 2;
    int am = m0 + arow;
    int tok;
    if (GATHER) tok = (am < cnt) ? g_rowlist[off + am] : 0;
    else        tok = (am < cnt) ? am : 0;
    const unsigned* ahp = g_xh + (size_t)tok * (ND / 2) + acb;
    const unsigned* alp = g_xl + (size_t)tok * (ND / 2) + acb;

    // B loader
    int mat = tid >> 7;
    int rr  = tid & 127;
    int kpw = rr >> 4;
    int nq  = (rr & 15) << 2;
    const float*    bp  = nullptr;
    const unsigned* bhp = nullptr;
    const unsigned* blp = nullptr;
    if (PRE_B) {
        bhp = (mat ? BUH : BGH) + (size_t)kpw * IDIM + n0 + nq;
        blp = (mat ? BUL : BGL) + (size_t)kpw * IDIM + n0 + nq;
    } else {
        const float* wsel = (mat ? Wu : Wg) + (size_t)e * ND * IDIM;
        bp = wsel + (size_t)(2 * kpw) * IDIM + n0 + nq;
    }
    unsigned* BHs = mat ? Buh : Bgh;
    unsigned* BLs = mat ? Bul : Bgl;

    float accg[2][4][4], accu[2][4][4];
    #pragma unroll
    for (int mt = 0; mt < 2; mt++)
        #pragma unroll
        for (int nt = 0; nt < 4; nt++)
            #pragma unroll
            for (int r = 0; r < 4; r++) { accg[mt][nt][r] = 0.f; accu[mt][nt][r] = 0.f; }

    uint4 rah = *(const uint4*)ahp;
    uint4 ral = *(const uint4*)alp;
    float4 rb0, rb1;
    uint4 rbh, rbl;
    if (PRE_B) { rbh = *(const uint4*)bhp; rbl = *(const uint4*)blp; }
    else       { rb0 = *(const float4*)bp; rb1 = *(const float4*)(bp + IDIM); }

    for (int kt = 0; kt < ND; kt += 16) {
        // ---- store A (pre-split, swizzled) ----
        {
            int s = arow & 7, base = arow * 8;
            Ah[base + ((acb + 0) ^ s)] = rah.x;
            Ah[base + ((acb + 1) ^ s)] = rah.y;
            Ah[base + ((acb + 2) ^ s)] = rah.z;
            Ah[base + ((acb + 3) ^ s)] = rah.w;
            Al[base + ((acb + 0) ^ s)] = ral.x;
            Al[base + ((acb + 1) ^ s)] = ral.y;
            Al[base + ((acb + 2) ^ s)] = ral.z;
            Al[base + ((acb + 3) ^ s)] = ral.w;
        }
        // ---- store B ----
        if (PRE_B) {
            *(uint4*)&BHs[kpw * B_STR + nq] = rbh;
            *(uint4*)&BLs[kpw * B_STR + nq] = rbl;
        } else {
            uint4 h, l;
            split2(rb0.x, rb1.x, h.x, l.x);
            split2(rb0.y, rb1.y, h.y, l.y);
            split2(rb0.z, rb1.z, h.z, l.z);
            split2(rb0.w, rb1.w, h.w, l.w);
            *(uint4*)&BHs[kpw * B_STR + nq] = h;
            *(uint4*)&BLs[kpw * B_STR + nq] = l;
        }
        __syncthreads();
        if (kt + 16 < ND) {
            rah = *(const uint4*)(ahp + (kt + 16) / 2);
            ral = *(const uint4*)(alp + (kt + 16) / 2);
            if (PRE_B) {
                rbh = *(const uint4*)(bhp + (size_t)((kt + 16) / 2) * IDIM);
                rbl = *(const uint4*)(blp + (size_t)((kt + 16) / 2) * IDIM);
            } else {
                rb0 = *(const float4*)(bp + (size_t)(kt + 16) * IDIM);
                rb1 = *(const float4*)(bp + (size_t)(kt + 17) * IDIM);
            }
        }
        // ---- fragments + mma ----
        {
            unsigned ah[2][4], al[2][4];
            #pragma unroll
            for (int mt = 0; mt < 2; mt++) {
                int R = warpM * 32 + mt * 16 + gq;
                int base = R * 8;
                int c0 = tq ^ gq, c1 = (tq + 4) ^ gq;
                ah[mt][0] = Ah[base + c0];
                ah[mt][1] = Ah[base + 64 + c0];
                ah[mt][2] = Ah[base + c1];
                ah[mt][3] = Ah[base + 64 + c1];
                al[mt][0] = Al[base + c0];
                al[mt][1] = Al[base + 64 + c0];
                al[mt][2] = Al[base + c1];
                al[mt][3] = Al[base + 64 + c1];
            }
            #pragma unroll
            for (int nt = 0; nt < 4; nt++) {
                int c = warpN * 32 + nt * 8 + gq;
                unsigned bgh[2], bgl[2], buh[2], bul[2];
                bgh[0] = Bgh[tq * B_STR + c]; bgh[1] = Bgh[(tq + 4) * B_STR + c];
                bgl[0] = Bgl[tq * B_STR + c]; bgl[1] = Bgl[(tq + 4) * B_STR + c];
                buh[0] = Buh[tq * B_STR + c]; buh[1] = Buh[(tq + 4) * B_STR + c];
                bul[0] = Bul[tq * B_STR + c]; bul[1] = Bul[(tq + 4) * B_STR + c];
                #pragma unroll
                for (int mt = 0; mt < 2; mt++) {
                    mma_bf16(accg[mt][nt], ah[mt], bgh);
                    mma_bf16(accg[mt][nt], al[mt], bgh);
                    mma_bf16(accg[mt][nt], ah[mt], bgl);
                    mma_bf16(accu[mt][nt], ah[mt], buh);
                    mma_bf16(accu[mt][nt], al[mt], buh);
                    mma_bf16(accu[mt][nt], ah[mt], bul);
                }
            }
        }
        __syncthreads();
    }
    // epilogue: silu(gate)*up, split to hi/lo, store packed u32
    #pragma unroll
    for (int mt = 0; mt < 2; mt++) {
        #pragma unroll
        for (int half = 0; half < 2; half++) {
            int r = m0 + warpM * 32 + mt * 16 + half * 8 + gq;
            if (r >= cnt) continue;
            size_t rowo = (size_t)(off + r) * (IDIM / 2);
            #pragma unroll
            for (int nt = 0; nt < 4; nt++) {
                float gv0 = accg[mt][nt][half * 2 + 0];
                float gv1 = accg[mt][nt][half * 2 + 1];
                float uv0 = accu[mt][nt][half * 2 + 0];
                float uv1 = accu[mt][nt][half * 2 + 1];
                float h0 = gv0 / (1.f + expf(-gv0)) * uv0;
                float h1 = gv1 / (1.f + expf(-gv1)) * uv1;
                unsigned hh_, hl_;
                split2(h0, h1, hh_, hl_);
                int hcol = (n0 >> 1) + warpN * 16 + nt * 4 + tq;
                HH[rowo + hcol] = hh_;
                HL[rowo + hcol] = hl_;
            }
        }
    }
}

// ---------------- GEMM 2: out (+)= H @ Wd ----------------
template<int IDIM, bool ROUTED, bool PRE_B>
__global__ void __launch_bounds__(256, 2)
gemm_down(const unsigned* __restrict__ AH, const unsigned* __restrict__ AL,
          const float* __restrict__ Wd,
          const unsigned* __restrict__ BHp, const unsigned* __restrict__ BLp,
          float* __restrict__ out) {
    int e   = ROUTED ? blockIdx.z : 0;
    int cnt = ROUTED ? g_counts[e]  : NT;
    int off = ROUTED ? g_offsets[e] : 0;
    int m0  = blockIdx.x * 128;
    if (m0 >= cnt) return;
    int n0  = blockIdx.y * 64;

    __shared__ unsigned Ah[128 * 8], Al[128 * 8];
    __shared__ unsigned Bh[8 * B_STR], Bl[8 * B_STR];

    int tid  = threadIdx.x;
    int lane = tid & 31, wid = tid >> 5;
    int warpM = wid >> 1, warpN = wid & 1;
    int gq = lane >> 2, tq = lane & 3;

    // A loader: pre-split H rows (stride IDIM/2 u32)
    int arow = tid >> 1, acb = (tid & 1) << 2;
    int am = m0 + arow;
    int hr = (am < cnt) ? (off + am) : off;
    const unsigned* ahp = AH + (size_t)hr * (IDIM / 2) + acb;
    const unsigned* alp = AL + (size_t)hr * (IDIM / 2) + acb;

    // B loader: first 128 threads
    int bact = (tid < 128);
    int kpw = (tid & 127) >> 4;
    int nq  = (tid & 15) << 2;
    const float*    bp  = nullptr;
    const unsigned* bhp = nullptr;
    const unsigned* blp = nullptr;
    if (PRE_B) {
        bhp = BHp + (size_t)kpw * ND + n0 + nq;
        blp = BLp + (size_t)kpw * ND + n0 + nq;
    } else {
        const float* wd = Wd + (size_t)e * IDIM * ND;
        bp = wd + (size_t)(2 * kpw) * ND + n0 + nq;
    }

    float acc[2][4][4];
    #pragma unroll
    for (int mt = 0; mt < 2; mt++)
        #pragma unroll
        for (int nt = 0; nt < 4; nt++)
            #pragma unroll
            for (int r = 0; r < 4; r++) acc[mt][nt][r] = 0.f;

    uint4 rah = *(const uint4*)ahp;
    uint4 ral = *(const uint4*)alp;
    float4 rb0, rb1;
    uint4 rbh, rbl;
    if (bact) {
        if (PRE_B) { rbh = *(const uint4*)bhp; rbl = *(const uint4*)blp; }
        else       { rb0 = *(const float4*)bp; rb1 = *(const float4*)(bp + ND); }
    }

    for (int kt = 0; kt < IDIM; kt += 16) {
        {
            int s = arow & 7, base = arow * 8;
            Ah[base + ((acb + 0) ^ s)] = rah.x;
            Ah[base + ((acb + 1) ^ s)] = rah.y;
            Ah[base + ((acb + 2) ^ s)] = rah.z;
            Ah[base + ((acb + 3) ^ s)] = rah.w;
            Al[base + ((acb + 0) ^ s)] = ral.x;
            Al[base + ((acb + 1) ^ s)] = ral.y;
            Al[base + ((acb + 2) ^ s)] = ral.z;
            Al[base + ((acb + 3) ^ s)] = ral.w;
        }
        if (bact) {
            if (PRE_B) {
                *(uint4*)&Bh[kpw * B_STR + nq] = rbh;
                *(uint4*)&Bl[kpw * B_STR + nq] = rbl;
            } else {
                uint4 h, l;
                split2(rb0.x, rb1.x, h.x, l.x);
                split2(rb0.y, rb1.y, h.y, l.y);
                split2(rb0.z, rb1.z, h.z, l.z);
                split2(rb0.w, rb1.w, h.w, l.w);
                *(uint4*)&Bh[kpw * B_STR + nq] = h;
                *(uint4*)&Bl[kpw * B_STR + nq] = l;
            }
        }
        __syncthreads();
        if (kt + 16 < IDIM) {
            rah = *(const uint4*)(ahp + (kt + 16) / 2);
            ral = *(const uint4*)(alp + (kt + 16) / 2);
            if (bact) {
                if (PRE_B) {
                    rbh = *(const uint4*)(bhp + (size_t)((kt + 16) / 2) * ND);
                    rbl = *(const uint4*)(blp + (size_t)((kt + 16) / 2) * ND);
                } else {
                    rb0 = *(const float4*)(bp + (size_t)(kt + 16) * ND);
                    rb1 = *(const float4*)(bp + (size_t)(kt + 17) * ND);
                }
            }
        }
        {
            unsigned ah[2][4], al[2][4];
            #pragma unroll
            for (int mt = 0; mt < 2; mt++) {
                int R = warpM * 32 + mt * 16 + gq;
                int base = R * 8;
                int c0 = tq ^ gq, c1 = (tq + 4) ^ gq;
                ah[mt][0] = Ah[base + c0];
                ah[mt][1] = Ah[base + 64 + c0];
                ah[mt][2] = Ah[base + c1];
                ah[mt][3] = Ah[base + 64 + c1];
                al[mt][0] = Al[base + c0];
                al[mt][1] = Al[base + 64 + c0];
                al[mt][2] = Al[base + c1];
                al[mt][3] = Al[base + 64 + c1];
            }
            #pragma unroll
            for (int nt = 0; nt < 4; nt++) {
                int c = warpN * 32 + nt * 8 + gq;
                unsigned bh[2], bl[2];
                bh[0] = Bh[tq * B_STR + c]; bh[1] = Bh[(tq + 4) * B_STR + c];
                bl[0] = Bl[tq * B_STR + c]; bl[1] = Bl[(tq + 4) * B_STR + c];
                #pragma unroll
                for (int mt = 0; mt < 2; mt++) {
                    mma_bf16(acc[mt][nt], ah[mt], bh);
                    mma_bf16(acc[mt][nt], al[mt], bh);
                    mma_bf16(acc[mt][nt], ah[mt], bl);
                }
            }
        }
        __syncthreads();
    }
    // epilogue
    #pragma unroll
    for (int mt = 0; mt < 2; mt++) {
        #pragma unroll
        for (int half = 0; half < 2; half++) {
            int r = m0 + warpM * 32 + mt * 16 + half * 8 + gq;
            if (r >= cnt) continue;
            if (ROUTED) {
                int grow = off + r;
                int tok  = g_rowlist[grow];
                float w  = g_roww[grow] * 2.5f;
                float* op = out + (size_t)tok * ND + n0 + warpN * 32;
                #pragma unroll
                for (int nt = 0; nt < 4; nt++) {
                    atomicAdd(&op[nt * 8 + 2 * tq],     w * acc[mt][nt][half * 2 + 0]);
                    atomicAdd(&op[nt * 8 + 2 * tq + 1], w * acc[mt][nt][half * 2 + 1]);
                }
            } else {
                float* op = out + (size_t)r * ND + n0 + warpN * 32;
                #pragma unroll
                for (int nt = 0; nt < 4; nt++) {
                    float2 v;
                    v.x = acc[mt][nt][half * 2 + 0];
                    v.y = acc[mt][nt][half * 2 + 1];
                    *(float2*)&op[nt * 8 + 2 * tq] = v;
                }
            }
        }
    }
}

// ---------------- launch ----------------
extern "C" void kernel_launch(void* const* d_in, const int* in_sizes, int n_in,
                              void* d_out, int out_size) {
    const float* x       = (const float*)d_in[0];
    const float* gate_w  = (const float*)d_in[1];
    const float* gate_b  = (const float*)d_in[2];
    const float* w_gate  = (const float*)d_in[3];
    const float* w_up    = (const float*)d_in[4];
    const float* w_down  = (const float*)d_in[5];
    const float* sw_gate = (const float*)d_in[6];
    const float* sw_up   = (const float*)d_in[7];
    const float* sw_down = (const float*)d_in[8];
    float* out = (float*)d_out;

    unsigned *xh, *xl, *hh, *hl, *hsh, *hsl, *sgh, *sgl, *suh, *sul, *sdh, *sdl;
    cudaGetSymbolAddress((void**)&xh,  g_xh);
    cudaGetSymbolAddress((void**)&xl,  g_xl);
    cudaGetSymbolAddress((void**)&hh,  g_hh);
    cudaGetSymbolAddress((void**)&hl,  g_hl);
    cudaGetSymbolAddress((void**)&hsh, g_hsh);
    cudaGetSymbolAddress((void**)&hsl, g_hsl);
    cudaGetSymbolAddress((void**)&sgh, g_sgh);
    cudaGetSymbolAddress((void**)&sgl, g_sgl);
    cudaGetSymbolAddress((void**)&suh, g_suh);
    cudaGetSymbolAddress((void**)&sul, g_sul);
    cudaGetSymbolAddress((void**)&sdh, g_sdh);
    cudaGetSymbolAddress((void**)&sdl, g_sdl);

    zero_kernel   <<<1, 32>>>();
    gate_kernel   <<<NT, 256>>>(x, gate_w, gate_b);
    scan_kernel   <<<1, 32>>>();
    scatter_kernel<<<NA / 256, 256>>>();

    // prologue splits
    split_x_kernel<<<(NT * ND / 4) / 256, 256>>>(x);
    split_w_kernel<<<((ND / 2) * (NSI / 4)) / 256, 256>>>(sw_gate, sgh, sgl, ND, NSI);
    split_w_kernel<<<((ND / 2) * (NSI / 4)) / 256, 256>>>(sw_up,   suh, sul, ND, NSI);
    split_w_kernel<<<((NSI / 2) * (ND / 4)) / 256, 256>>>(sw_down, sdh, sdl, NSI, ND);

    // shared expert gate/up (pre-split B)
    gemm_gated<NSI, false, true><<<dim3(NT / 128, NSI / 64, 1), 256>>>(
        nullptr, nullptr, sgh, sgl, suh, sul, hsh, hsl);
    // routed experts gate/up (inline B split)
    gemm_gated<NI, true, false><<<dim3(NT / 128, NI / 64, NE), 256>>>(
        w_gate, w_up, nullptr, nullptr, nullptr, nullptr, hh, hl);
    // shared down-proj: plain stores initialize out
    gemm_down<NSI, false, true><<<dim3(NT / 128, ND / 64, 1), 256>>>(
        hsh, hsl, nullptr, sdh, sdl, out);
    // routed down-proj: weighted atomic accumulation
    gemm_down<NI, true, false><<<dim3(NT / 128, ND / 64, NE), 256>>>(
        hh, hl, w_down, nullptr, nullptr, out);
}

// round 10
// speedup vs baseline: 1.3470x; 1.3428x over previous
#include <cuda_runtime.h>
#include <math.h>
#include <stdint.h>

// Problem constants
#define NT   1024          // tokens
#define ND   2048          // hidden dim
#define NE   32            // experts
#define NI   1408          // routed intermediate
#define NSI  2816          // shared intermediate
#define NG   8             // groups
#define EPG  4             // experts per group
#define NA   (NT * 4)      // total assignments (top_k = 4)

// ---------------- device scratch ----------------
__device__ float g_h [NA * NI];    // routed  silu(x@Wg)*(x@Wu)  (fp32)
__device__ float g_hs[NT * NSI];   // shared  silu(x@Sg)*(x@Su)
__device__ int   g_rowlist[NA];
__device__ float g_roww  [NA];
__device__ int   g_counts [NE];
__device__ int   g_offsets[NE];
__device__ int   g_cursor [NE];
__device__ int   g_tid4[NA];
__device__ float g_tw4 [NA];

// ---------------- bf16 split + mma helpers ----------------
// v = hi + lo (bf16 each). Packs (v0, v1) -> u32 with v0 in low half.
__device__ __forceinline__ void split2(float v0, float v1, unsigned& h, unsigned& l) {
    unsigned hh;
    asm("cvt.rn.bf16x2.f32 %0, %1, %2;" : "=r"(hh) : "f"(v1), "f"(v0));
    float h0 = __uint_as_float(hh << 16);
    float h1 = __uint_as_float(hh & 0xffff0000u);
    asm("cvt.rn.bf16x2.f32 %0, %1, %2;" : "=r"(l) : "f"(v1 - h1), "f"(v0 - h0));
    h = hh;
}

__device__ __forceinline__ void mma_bf16(float* d, const unsigned* a, const unsigned* b) {
    asm volatile(
        "mma.sync.aligned.m16n8k16.row.col.f32.bf16.bf16.f32 "
        "{%0,%1,%2,%3}, {%4,%5,%6,%7}, {%8,%9}, {%0,%1,%2,%3};"
        : "+f"(d[0]), "+f"(d[1]), "+f"(d[2]), "+f"(d[3])
        : "r"(a[0]), "r"(a[1]), "r"(a[2]), "r"(a[3]), "r"(b[0]), "r"(b[1]));
}

__device__ __forceinline__ void ldsm4(unsigned* r, uint32_t a) {
    asm volatile("ldmatrix.sync.aligned.m8n8.x4.shared.b16 {%0,%1,%2,%3}, [%4];"
        : "=r"(r[0]), "=r"(r[1]), "=r"(r[2]), "=r"(r[3]) : "r"(a));
}
__device__ __forceinline__ void ldsm4t(unsigned* r, uint32_t a) {
    asm volatile("ldmatrix.sync.aligned.m8n8.x4.trans.shared.b16 {%0,%1,%2,%3}, [%4];"
        : "=r"(r[0]), "=r"(r[1]), "=r"(r[2]), "=r"(r[3]) : "r"(a));
}
__device__ __forceinline__ uint32_t sptr(const void* p) {
    return (uint32_t)__cvta_generic_to_shared(p);
}

// ---------------- routing kernels ----------------
__global__ void zero_kernel() {
    int i = threadIdx.x;
    if (i < NE) { g_counts[i] = 0; g_cursor[i] = 0; }
}

__global__ void gate_kernel(const float* __restrict__ x,
                            const float* __restrict__ gw,
                            const float* __restrict__ gb) {
    __shared__ float xs[ND];
    __shared__ float logit[NE];
    int t = blockIdx.x;
    for (int k = threadIdx.x; k < ND; k += 256) xs[k] = x[(size_t)t * ND + k];
    __syncthreads();
    int e = threadIdx.x >> 3;
    int j = threadIdx.x & 7;
    const float* w = gw + (size_t)e * ND;
    float s = 0.f;
    for (int k = j; k < ND; k += 8) s += xs[k] * w[k];
    s += __shfl_xor_sync(0xffffffffu, s, 1);
    s += __shfl_xor_sync(0xffffffffu, s, 2);
    s += __shfl_xor_sync(0xffffffffu, s, 4);
    if (j == 0) logit[e] = s + gb[e];
    __syncthreads();
    if (threadIdx.x == 0) {
        float sc[NE], scb[NE];
        #pragma unroll
        for (int i = 0; i < NE; i++) {
            float v = 1.f / (1.f + expf(-logit[i]));
            sc[i]  = v;
            scb[i] = v + gb[i];
        }
        float gs[NG];
        #pragma unroll
        for (int g = 0; g < NG; g++) {
            float m1 = -1e30f, m2 = -1e30f;
            #pragma unroll
            for (int q = 0; q < EPG; q++) {
                float v = scb[g * EPG + q];
                if (v > m1) { m2 = m1; m1 = v; } else if (v > m2) { m2 = v; }
            }
            gs[g] = m1 + m2;
        }
        bool gsel[NG];
        #pragma unroll
        for (int g = 0; g < NG; g++) gsel[g] = false;
        for (int r = 0; r < 4; r++) {
            float best = -1e30f; int bi = 0;
            for (int g = 0; g < NG; g++)
                if (!gsel[g] && gs[g] > best) { best = gs[g]; bi = g; }
            gsel[bi] = true;
        }
        float tmp[NE];
        #pragma unroll
        for (int i = 0; i < NE; i++) tmp[i] = gsel[i / EPG] ? scb[i] : 0.0f;
        int ids[4]; float tw[4]; float wsum = 0.f;
        for (int r = 0; r < 4; r++) {
            float best = -1e30f; int bi = 0;
            for (int i = 0; i < NE; i++)
                if (tmp[i] > best) { best = tmp[i]; bi = i; }
            tmp[bi] = -1e30f;
            ids[r] = bi;
            tw[r] = sc[bi];
            wsum += tw[r];
        }
        float inv = 1.f / wsum;
        for (int r = 0; r < 4; r++) {
            g_tid4[t * 4 + r] = ids[r];
            g_tw4 [t * 4 + r] = tw[r] * inv;
            atomicAdd(&g_counts[ids[r]], 1);
        }
    }
}

__global__ void scan_kernel() {
    int tid = threadIdx.x;
    int c = g_counts[tid];
    int v = c;
    #pragma unroll
    for (int o = 1; o < 32; o <<= 1) {
        int u = __shfl_up_sync(0xffffffffu, v, o);
        if (tid >= o) v += u;
    }
    g_offsets[tid] = v - c;
}

__global__ void scatter_kernel() {
    int i = blockIdx.x * blockDim.x + threadIdx.x;
    if (i >= NA) return;
    int t = i >> 2;
    int e = g_tid4[i];
    int pos = atomicAdd(&g_cursor[e], 1);
    int row = g_offsets[e] + pos;
    g_rowlist[row] = t;
    g_roww[row]   = g_tw4[i];
}

// ============================================================================
// bf16x3 mma.sync GEMMs with LDSM fragment loading.
// Block BM=128, BN=64, BK=16; 256 thr = 8 warps (4M x 2N); warp tile 32x32.
// A SMEM: [128 rows][24 bf16] (stride 48B -> LDSM conflict-free; cols 0..15 used)
// B SMEM: [16 k-rows][72 bf16] (stride 144B -> conflict-free; cols 0..63 used)
// A frags: ldmatrix.x4 ; B frags: ldmatrix.x4.trans (two n-tiles per issue).
// bf16x3: acc += Ah*Bh + Al*Bh + Ah*Bl  (fp32 accum, same numerics as R6).
// ============================================================================

#define A_STR 24
#define B_STR 72

// ---------------- GEMM 1: H = silu(A@Wg) * (A@Wu) ----------------
template<int IDIM, bool GATHER>
__global__ void __launch_bounds__(256, 2)
gemm_gated(const float* __restrict__ x,
           const float* __restrict__ Wg,
           const float* __restrict__ Wu) {
    int e   = GATHER ? blockIdx.z : 0;
    int cnt = GATHER ? g_counts[e]  : NT;
    int off = GATHER ? g_offsets[e] : 0;
    int m0  = blockIdx.x * 128;
    if (m0 >= cnt) return;
    int n0  = blockIdx.y * 64;
    float* H = GATHER ? g_h : g_hs;

    __shared__ __align__(16) unsigned short Ah[128 * A_STR], Al[128 * A_STR];
    __shared__ __align__(16) unsigned short Bgh[16 * B_STR], Bgl[16 * B_STR];
    __shared__ __align__(16) unsigned short Buh[16 * B_STR], Bul[16 * B_STR];

    int tid  = threadIdx.x;
    int lane = tid & 31, wid = tid >> 5;
    int warpM = wid >> 1, warpN = wid & 1;
    int gq = lane >> 2, tq = lane & 3;

    // ---- A staging: 2 float4 per thread over 128x16 fp32 ----
    const float* aptr[2]; int mA[2], kA[2];
    #pragma unroll
    for (int l = 0; l < 2; l++) {
        int idx = tid + l * 256;
        mA[l] = idx >> 2; kA[l] = (idx & 3) << 2;
        int m = m0 + mA[l];
        int tok;
        if (GATHER) tok = (m < cnt) ? g_rowlist[off + m] : 0;
        else        tok = (m < cnt) ? m : 0;
        aptr[l] = x + (size_t)tok * ND + kA[l];
    }
    // ---- B staging: 2 matrices x 128 threads; thread: rows kr, kr+8; 4 n-vals
    int mat = tid >> 7, rr = tid & 127;
    int kr  = rr >> 4, nq = (rr & 15) << 2;
    const float* bp = (mat ? Wu : Wg) + (size_t)e * ND * IDIM
                      + (size_t)kr * IDIM + n0 + nq;
    unsigned short* BH = mat ? Buh : Bgh;
    unsigned short* BL = mat ? Bul : Bgl;

    // ---- LDSM addresses (constant across K loop) ----
    int arow = lane & 15, acolb = (lane >> 4) << 4;  // byte col offset 0/16
    uint32_t a_ld_h[2], a_ld_l[2];
    #pragma unroll
    for (int mt = 0; mt < 2; mt++) {
        int r = warpM * 32 + mt * 16 + arow;
        a_ld_h[mt] = sptr(Ah) + r * (A_STR * 2) + acolb;
        a_ld_l[mt] = sptr(Al) + r * (A_STR * 2) + acolb;
    }
    int bkr = lane & 15;
    int bcolb = (warpN * 32) * 2 + ((lane >> 4) << 4); // bytes within row
    uint32_t b_ld[4][2];
    const unsigned short* barr[4] = {Bgh, Bgl, Buh, Bul};
    #pragma unroll
    for (int a = 0; a < 4; a++)
        #pragma unroll
        for (int np = 0; np < 2; np++)
            b_ld[a][np] = sptr(barr[a]) + bkr * (B_STR * 2) + bcolb + np * 32;

    float accg[2][4][4], accu[2][4][4];
    #pragma unroll
    for (int mt = 0; mt < 2; mt++)
        #pragma unroll
        for (int nt = 0; nt < 4; nt++)
            #pragma unroll
            for (int r = 0; r < 4; r++) { accg[mt][nt][r] = 0.f; accu[mt][nt][r] = 0.f; }

    float4 ra0 = *(const float4*)(aptr[0]);
    float4 ra1 = *(const float4*)(aptr[1]);
    float4 rb0 = *(const float4*)(bp);
    float4 rb1 = *(const float4*)(bp + (size_t)8 * IDIM);

    for (int kt = 0; kt < ND; kt += 16) {
        // store A (row-major bf16)
        {
            unsigned h0, l0, h1, l1;
            split2(ra0.x, ra0.y, h0, l0); split2(ra0.z, ra0.w, h1, l1);
            *(uint2*)&Ah[mA[0] * A_STR + kA[0]] = make_uint2(h0, h1);
            *(uint2*)&Al[mA[0] * A_STR + kA[0]] = make_uint2(l0, l1);
            split2(ra1.x, ra1.y, h0, l0); split2(ra1.z, ra1.w, h1, l1);
            *(uint2*)&Ah[mA[1] * A_STR + kA[1]] = make_uint2(h0, h1);
            *(uint2*)&Al[mA[1] * A_STR + kA[1]] = make_uint2(l0, l1);
        }
        // store B rows kr and kr+8 (row-major bf16 [k][n])
        {
            unsigned h0, l0, h1, l1;
            split2(rb0.x, rb0.y, h0, l0); split2(rb0.z, rb0.w, h1, l1);
            *(uint2*)&BH[kr * B_STR + nq] = make_uint2(h0, h1);
            *(uint2*)&BL[kr * B_STR + nq] = make_uint2(l0, l1);
            split2(rb1.x, rb1.y, h0, l0); split2(rb1.z, rb1.w, h1, l1);
            *(uint2*)&BH[(kr + 8) * B_STR + nq] = make_uint2(h0, h1);
            *(uint2*)&BL[(kr + 8) * B_STR + nq] = make_uint2(l0, l1);
        }
        __syncthreads();
        if (kt + 16 < ND) {
            ra0 = *(const float4*)(aptr[0] + kt + 16);
            ra1 = *(const float4*)(aptr[1] + kt + 16);
            rb0 = *(const float4*)(bp + (size_t)(kt + 16) * IDIM);
            rb1 = *(const float4*)(bp + (size_t)(kt + 24) * IDIM);
        }
        // fragments + mma
        {
            unsigned ah[2][4], al[2][4];
            ldsm4(ah[0], a_ld_h[0]); ldsm4(ah[1], a_ld_h[1]);
            ldsm4(al[0], a_ld_l[0]); ldsm4(al[1], a_ld_l[1]);
            #pragma unroll
            for (int np = 0; np < 2; np++) {
                unsigned bgh[4], bgl[4], buh[4], bul[4];
                ldsm4t(bgh, b_ld[0][np]); ldsm4t(bgl, b_ld[1][np]);
                ldsm4t(buh, b_ld[2][np]); ldsm4t(bul, b_ld[3][np]);
                #pragma unroll
                for (int j = 0; j < 2; j++) {
                    int nt = np * 2 + j;
                    #pragma unroll
                    for (int mt = 0; mt < 2; mt++) {
                        mma_bf16(accg[mt][nt], ah[mt], &bgh[2 * j]);
                        mma_bf16(accg[mt][nt], al[mt], &bgh[2 * j]);
                        mma_bf16(accg[mt][nt], ah[mt], &bgl[2 * j]);
                        mma_bf16(accu[mt][nt], ah[mt], &buh[2 * j]);
                        mma_bf16(accu[mt][nt], al[mt], &buh[2 * j]);
                        mma_bf16(accu[mt][nt], ah[mt], &bul[2 * j]);
                    }
                }
            }
        }
        __syncthreads();
    }
    // epilogue: silu(gate) * up -> fp32 H
    #pragma unroll
    for (int mt = 0; mt < 2; mt++) {
        #pragma unroll
        for (int half = 0; half < 2; half++) {
            int r = m0 + warpM * 32 + mt * 16 + half * 8 + gq;
            if (r >= cnt) continue;
            float* hrow = H + (size_t)(off + r) * IDIM + n0 + warpN * 32;
            #pragma unroll
            for (int nt = 0; nt < 4; nt++) {
                float gv0 = accg[mt][nt][half * 2 + 0];
                float gv1 = accg[mt][nt][half * 2 + 1];
                float uv0 = accu[mt][nt][half * 2 + 0];
                float uv1 = accu[mt][nt][half * 2 + 1];
                float2 hv;
                hv.x = gv0 / (1.f + expf(-gv0)) * uv0;
                hv.y = gv1 / (1.f + expf(-gv1)) * uv1;
                *(float2*)&hrow[nt * 8 + 2 * tq] = hv;
            }
        }
    }
}

// ---------------- GEMM 2: out (+)= H @ Wd ----------------
template<int IDIM, bool ROUTED>
__global__ void __launch_bounds__(256, 2)
gemm_down(const float* __restrict__ Wd,
          float* __restrict__ out) {
    int e   = ROUTED ? blockIdx.z : 0;
    int cnt = ROUTED ? g_counts[e]  : NT;
    int off = ROUTED ? g_offsets[e] : 0;
    int m0  = blockIdx.x * 128;
    if (m0 >= cnt) return;
    int n0  = blockIdx.y * 64;
    const float* wd = Wd + (size_t)e * IDIM * ND;
    const float* Hsrc = ROUTED ? g_h : g_hs;

    __shared__ __align__(16) unsigned short Ah[128 * A_STR], Al[128 * A_STR];
    __shared__ __align__(16) unsigned short Bh[16 * B_STR], Bl[16 * B_STR];

    int tid  = threadIdx.x;
    int lane = tid & 31, wid = tid >> 5;
    int warpM = wid >> 1, warpN = wid & 1;
    int gq = lane >> 2, tq = lane & 3;

    const float* aptr[2]; int mA[2], kA[2];
    #pragma unroll
    for (int l = 0; l < 2; l++) {
        int idx = tid + l * 256;
        mA[l] = idx >> 2; kA[l] = (idx & 3) << 2;
        int m = m0 + mA[l];
        int hr = (m < cnt) ? (off + m) : off;
        aptr[l] = Hsrc + (size_t)hr * IDIM + kA[l];
    }
    // B staging: 256 threads, one k-row each
    int kr = tid >> 4, nq = (tid & 15) << 2;
    const float* bp = wd + (size_t)kr * ND + n0 + nq;

    int arow = lane & 15, acolb = (lane >> 4) << 4;
    uint32_t a_ld_h[2], a_ld_l[2];
    #pragma unroll
    for (int mt = 0; mt < 2; mt++) {
        int r = warpM * 32 + mt * 16 + arow;
        a_ld_h[mt] = sptr(Ah) + r * (A_STR * 2) + acolb;
        a_ld_l[mt] = sptr(Al) + r * (A_STR * 2) + acolb;
    }
    int bkr = lane & 15;
    int bcolb = (warpN * 32) * 2 + ((lane >> 4) << 4);
    uint32_t b_ld_h[2], b_ld_l[2];
    #pragma unroll
    for (int np = 0; np < 2; np++) {
        b_ld_h[np] = sptr(Bh) + bkr * (B_STR * 2) + bcolb + np * 32;
        b_ld_l[np] = sptr(Bl) + bkr * (B_STR * 2) + bcolb + np * 32;
    }

    float acc[2][4][4];
    #pragma unroll
    for (int mt = 0; mt < 2; mt++)
        #pragma unroll
        for (int nt = 0; nt < 4; nt++)
            #pragma unroll
            for (int r = 0; r < 4; r++) acc[mt][nt][r] = 0.f;

    float4 ra0 = *(const float4*)(aptr[0]);
    float4 ra1 = *(const float4*)(aptr[1]);
    float4 rb  = *(const float4*)(bp);

    for (int kt = 0; kt < IDIM; kt += 16) {
        {
            unsigned h0, l0, h1, l1;
            split2(ra0.x, ra0.y, h0, l0); split2(ra0.z, ra0.w, h1, l1);
            *(uint2*)&Ah[mA[0] * A_STR + kA[0]] = make_uint2(h0, h1);
            *(uint2*)&Al[mA[0] * A_STR + kA[0]] = make_uint2(l0, l1);
            split2(ra1.x, ra1.y, h0, l0); split2(ra1.z, ra1.w, h1, l1);
            *(uint2*)&Ah[mA[1] * A_STR + kA[1]] = make_uint2(h0, h1);
            *(uint2*)&Al[mA[1] * A_STR + kA[1]] = make_uint2(l0, l1);
        }
        {
            unsigned h0, l0, h1, l1;
            split2(rb.x, rb.y, h0, l0); split2(rb.z, rb.w, h1, l1);
            *(uint2*)&Bh[kr * B_STR + nq] = make_uint2(h0, h1);
            *(uint2*)&Bl[kr * B_STR + nq] = make_uint2(l0, l1);
        }
        __syncthreads();
        if (kt + 16 < IDIM) {
            ra0 = *(const float4*)(aptr[0] + kt + 16);
            ra1 = *(const float4*)(aptr[1] + kt + 16);
            rb  = *(const float4*)(bp + (size_t)(kt + 16) * ND);
        }
        {
            unsigned ah[2][4], al[2][4];
            ldsm4(ah[0], a_ld_h[0]); ldsm4(ah[1], a_ld_h[1]);
            ldsm4(al[0], a_ld_l[0]); ldsm4(al[1], a_ld_l[1]);
            #pragma unroll
            for (int np = 0; np < 2; np++) {
                unsigned bh[4], bl[4];
                ldsm4t(bh, b_ld_h[np]); ldsm4t(bl, b_ld_l[np]);
                #pragma unroll
                for (int j = 0; j < 2; j++) {
                    int nt = np * 2 + j;
                    #pragma unroll
                    for (int mt = 0; mt < 2; mt++) {
                        mma_bf16(acc[mt][nt], ah[mt], &bh[2 * j]);
                        mma_bf16(acc[mt][nt], al[mt], &bh[2 * j]);
                        mma_bf16(acc[mt][nt], ah[mt], &bl[2 * j]);
                    }
                }
            }
        }
        __syncthreads();
    }
    // epilogue
    #pragma unroll
    for (int mt = 0; mt < 2; mt++) {
        #pragma unroll
        for (int half = 0; half < 2; half++) {
            int r = m0 + warpM * 32 + mt * 16 + half * 8 + gq;
            if (r >= cnt) continue;
            if (ROUTED) {
                int grow = off + r;
                int tok  = g_rowlist[grow];
                float w  = g_roww[grow] * 2.5f;
                float* op = out + (size_t)tok * ND + n0 + warpN * 32;
                #pragma unroll
                for (int nt = 0; nt < 4; nt++) {
                    atomicAdd(&op[nt * 8 + 2 * tq],     w * acc[mt][nt][half * 2 + 0]);
                    atomicAdd(&op[nt * 8 + 2 * tq + 1], w * acc[mt][nt][half * 2 + 1]);
                }
            } else {
                float* op = out + (size_t)r * ND + n0 + warpN * 32;
                #pragma unroll
                for (int nt = 0; nt < 4; nt++) {
                    float2 v;
                    v.x = acc[mt][nt][half * 2 + 0];
                    v.y = acc[mt][nt][half * 2 + 1];
                    *(float2*)&op[nt * 8 + 2 * tq] = v;
                }
            }
        }
    }
}

// ---------------- launch ----------------
extern "C" void kernel_launch(void* const* d_in, const int* in_sizes, int n_in,
                              void* d_out, int out_size) {
    const float* x       = (const float*)d_in[0];
    const float* gate_w  = (const float*)d_in[1];
    const float* gate_b  = (const float*)d_in[2];
    const float* w_gate  = (const float*)d_in[3];
    const float* w_up    = (const float*)d_in[4];
    const float* w_down  = (const float*)d_in[5];
    const float* sw_gate = (const float*)d_in[6];
    const float* sw_up   = (const float*)d_in[7];
    const float* sw_down = (const float*)d_in[8];
    float* out = (float*)d_out;

    zero_kernel   <<<1, 32>>>();
    gate_kernel   <<<NT, 256>>>(x, gate_w, gate_b);
    scan_kernel   <<<1, 32>>>();
    scatter_kernel<<<NA / 256, 256>>>();

    // shared expert gate/up
    gemm_gated<NSI, false><<<dim3(NT / 128, NSI / 64, 1), 256>>>(x, sw_gate, sw_up);
    // routed experts gate/up
    gemm_gated<NI,  true ><<<dim3(NT / 128, NI  / 64, NE), 256>>>(x, w_gate, w_up);
    // shared down-proj: plain stores initialize out
    gemm_down<NSI, false><<<dim3(NT / 128, ND / 64, 1), 256>>>(sw_down, out);
    // routed down-proj: weighted atomic accumulation
    gemm_down<NI,  true ><<<dim3(NT / 128, ND / 64, NE), 256>>>(w_down, out);
}

// round 11
// speedup vs baseline: 1.5238x; 1.1313x over previous
#include <cuda_runtime.h>
#include <math.h>
#include <stdint.h>

// Problem constants
#define NT   1024          // tokens
#define ND   2048          // hidden dim
#define NE   32            // experts
#define NI   1408          // routed intermediate
#define NSI  2816          // shared intermediate
#define NG   8             // groups
#define EPG  4             // experts per group
#define NA   (NT * 4)      // total assignments (top_k = 4)

// ---------------- device scratch ----------------
__device__ float g_h [NA * NI];    // routed  silu(x@Wg)*(x@Wu)  (fp32)
__device__ float g_hs[NT * NSI];   // shared  silu(x@Sg)*(x@Su)
__device__ int   g_rowlist[NA];
__device__ float g_roww  [NA];
__device__ int   g_counts [NE];
__device__ int   g_offsets[NE];
__device__ int   g_cursor [NE];
__device__ int   g_tid4[NA];
__device__ float g_tw4 [NA];

// ---------------- bf16 split + mma helpers ----------------
// v = hi + lo (bf16 each). Packs (v0, v1) -> u32 with v0 in low half.
__device__ __forceinline__ void split2(float v0, float v1, unsigned& h, unsigned& l) {
    unsigned hh;
    asm("cvt.rn.bf16x2.f32 %0, %1, %2;" : "=r"(hh) : "f"(v1), "f"(v0));
    float h0 = __uint_as_float(hh << 16);
    float h1 = __uint_as_float(hh & 0xffff0000u);
    asm("cvt.rn.bf16x2.f32 %0, %1, %2;" : "=r"(l) : "f"(v1 - h1), "f"(v0 - h0));
    h = hh;
}

__device__ __forceinline__ void mma_bf16(float* d, const unsigned* a, const unsigned* b) {
    asm volatile(
        "mma.sync.aligned.m16n8k16.row.col.f32.bf16.bf16.f32 "
        "{%0,%1,%2,%3}, {%4,%5,%6,%7}, {%8,%9}, {%0,%1,%2,%3};"
        : "+f"(d[0]), "+f"(d[1]), "+f"(d[2]), "+f"(d[3])
        : "r"(a[0]), "r"(a[1]), "r"(a[2]), "r"(a[3]), "r"(b[0]), "r"(b[1]));
}

__device__ __forceinline__ void ldsm4(unsigned* r, uint32_t a) {
    asm volatile("ldmatrix.sync.aligned.m8n8.x4.shared.b16 {%0,%1,%2,%3}, [%4];"
        : "=r"(r[0]), "=r"(r[1]), "=r"(r[2]), "=r"(r[3]) : "r"(a));
}
__device__ __forceinline__ void ldsm4t(unsigned* r, uint32_t a) {
    asm volatile("ldmatrix.sync.aligned.m8n8.x4.trans.shared.b16 {%0,%1,%2,%3}, [%4];"
        : "=r"(r[0]), "=r"(r[1]), "=r"(r[2]), "=r"(r[3]) : "r"(a));
}
__device__ __forceinline__ uint32_t sptr(const void* p) {
    return (uint32_t)__cvta_generic_to_shared(p);
}

// ---------------- routing kernels ----------------
__global__ void zero_kernel() {
    int i = threadIdx.x;
    if (i < NE) { g_counts[i] = 0; g_cursor[i] = 0; }
}

__global__ void gate_kernel(const float* __restrict__ x,
                            const float* __restrict__ gw,
                            const float* __restrict__ gb) {
    __shared__ float xs[ND];
    __shared__ float logit[NE];
    int t = blockIdx.x;
    for (int k = threadIdx.x; k < ND; k += 256) xs[k] = x[(size_t)t * ND + k];
    __syncthreads();
    int e = threadIdx.x >> 3;
    int j = threadIdx.x & 7;
    const float* w = gw + (size_t)e * ND;
    float s = 0.f;
    for (int k = j; k < ND; k += 8) s += xs[k] * w[k];
    s += __shfl_xor_sync(0xffffffffu, s, 1);
    s += __shfl_xor_sync(0xffffffffu, s, 2);
    s += __shfl_xor_sync(0xffffffffu, s, 4);
    if (j == 0) logit[e] = s + gb[e];
    __syncthreads();
    if (threadIdx.x == 0) {
        float sc[NE], scb[NE];
        #pragma unroll
        for (int i = 0; i < NE; i++) {
            float v = 1.f / (1.f + expf(-logit[i]));
            sc[i]  = v;
            scb[i] = v + gb[i];
        }
        float gs[NG];
        #pragma unroll
        for (int g = 0; g < NG; g++) {
            float m1 = -1e30f, m2 = -1e30f;
            #pragma unroll
            for (int q = 0; q < EPG; q++) {
                float v = scb[g * EPG + q];
                if (v > m1) { m2 = m1; m1 = v; } else if (v > m2) { m2 = v; }
            }
            gs[g] = m1 + m2;
        }
        bool gsel[NG];
        #pragma unroll
        for (int g = 0; g < NG; g++) gsel[g] = false;
        for (int r = 0; r < 4; r++) {
            float best = -1e30f; int bi = 0;
            for (int g = 0; g < NG; g++)
                if (!gsel[g] && gs[g] > best) { best = gs[g]; bi = g; }
            gsel[bi] = true;
        }
        float tmp[NE];
        #pragma unroll
        for (int i = 0; i < NE; i++) tmp[i] = gsel[i / EPG] ? scb[i] : 0.0f;
        int ids[4]; float tw[4]; float wsum = 0.f;
        for (int r = 0; r < 4; r++) {
            float best = -1e30f; int bi = 0;
            for (int i = 0; i < NE; i++)
                if (tmp[i] > best) { best = tmp[i]; bi = i; }
            tmp[bi] = -1e30f;
            ids[r] = bi;
            tw[r] = sc[bi];
            wsum += tw[r];
        }
        float inv = 1.f / wsum;
        for (int r = 0; r < 4; r++) {
            g_tid4[t * 4 + r] = ids[r];
            g_tw4 [t * 4 + r] = tw[r] * inv;
            atomicAdd(&g_counts[ids[r]], 1);
        }
    }
}

__global__ void scan_kernel() {
    int tid = threadIdx.x;
    int c = g_counts[tid];
    int v = c;
    #pragma unroll
    for (int o = 1; o < 32; o <<= 1) {
        int u = __shfl_up_sync(0xffffffffu, v, o);
        if (tid >= o) v += u;
    }
    g_offsets[tid] = v - c;
}

__global__ void scatter_kernel() {
    int i = blockIdx.x * blockDim.x + threadIdx.x;
    if (i >= NA) return;
    int t = i >> 2;
    int e = g_tid4[i];
    int pos = atomicAdd(&g_cursor[e], 1);
    int row = g_offsets[e] + pos;
    g_rowlist[row] = t;
    g_roww[row]   = g_tw4[i];
}

// ============================================================================
// bf16x3 mma.sync GEMMs, LDSM fragments, 2-stage SMEM ping-pong (1 sync/chunk).
// Block BM=128, BN=64, BK=16; 256 thr = 8 warps (4M x 2N); warp tile 32x32.
// A SMEM: [2][128][24 bf16] (stride 48B, LDSM conflict-free; cols 0..15 used)
// B SMEM: [2][16][72 bf16]  (stride 144B, conflict-free; cols 0..63 used)
// bf16x3: acc += Ah*Bh + Al*Bh + Ah*Bl  (fp32 accum).
// ============================================================================

#define A_STR 24
#define B_STR 72
#define A_SZ  (128 * A_STR)   // elements per stage
#define B_SZ  (16 * B_STR)
#define A_SZB (A_SZ * 2)      // bytes per stage
#define B_SZB (B_SZ * 2)

// ---------------- GEMM 1: H = silu(A@Wg) * (A@Wu) ----------------
template<int IDIM, bool GATHER>
__global__ void __launch_bounds__(256, 2)
gemm_gated(const float* __restrict__ x,
           const float* __restrict__ Wg,
           const float* __restrict__ Wu) {
    int e   = GATHER ? blockIdx.z : 0;
    int cnt = GATHER ? g_counts[e]  : NT;
    int off = GATHER ? g_offsets[e] : 0;
    int m0  = blockIdx.x * 128;
    if (m0 >= cnt) return;
    int n0  = blockIdx.y * 64;
    float* H = GATHER ? g_h : g_hs;

    __shared__ __align__(16) unsigned short Ah[2][A_SZ], Al[2][A_SZ];
    __shared__ __align__(16) unsigned short Bgh[2][B_SZ], Bgl[2][B_SZ];
    __shared__ __align__(16) unsigned short Buh[2][B_SZ], Bul[2][B_SZ];

    int tid  = threadIdx.x;
    int lane = tid & 31, wid = tid >> 5;
    int warpM = wid >> 1, warpN = wid & 1;
    int gq = lane >> 2, tq = lane & 3;

    // ---- A staging: 2 float4 per thread over 128x16 fp32 ----
    const float* aptr[2]; int mA[2], kA[2];
    #pragma unroll
    for (int l = 0; l < 2; l++) {
        int idx = tid + l * 256;
        mA[l] = idx >> 2; kA[l] = (idx & 3) << 2;
        int m = m0 + mA[l];
        int tok;
        if (GATHER) tok = (m < cnt) ? g_rowlist[off + m] : 0;
        else        tok = (m < cnt) ? m : 0;
        aptr[l] = x + (size_t)tok * ND + kA[l];
    }
    // ---- B staging: 2 matrices x 128 threads; thread: rows kr, kr+8; 4 n-vals
    int mat = tid >> 7, rr = tid & 127;
    int kr  = rr >> 4, nq = (rr & 15) << 2;
    const float* bp = (mat ? Wu : Wg) + (size_t)e * ND * IDIM
                      + (size_t)kr * IDIM + n0 + nq;
    unsigned short* BH0 = mat ? Buh[0] : Bgh[0];
    unsigned short* BL0 = mat ? Bul[0] : Bgl[0];

    // ---- LDSM base addresses (stage 0); stage offset added in loop ----
    int arow = lane & 15, acolb = (lane >> 4) << 4;
    uint32_t a_ld_h[2], a_ld_l[2];
    #pragma unroll
    for (int mt = 0; mt < 2; mt++) {
        int r = warpM * 32 + mt * 16 + arow;
        a_ld_h[mt] = sptr(Ah) + r * (A_STR * 2) + acolb;
        a_ld_l[mt] = sptr(Al) + r * (A_STR * 2) + acolb;
    }
    int bkr = lane & 15;
    int bcolb = (warpN * 32) * 2 + ((lane >> 4) << 4);
    uint32_t b_ld[4][2];
    const void* barr[4] = {Bgh, Bgl, Buh, Bul};
    #pragma unroll
    for (int a = 0; a < 4; a++)
        #pragma unroll
        for (int np = 0; np < 2; np++)
            b_ld[a][np] = sptr(barr[a]) + bkr * (B_STR * 2) + bcolb + np * 32;

    float accg[2][4][4], accu[2][4][4];
    #pragma unroll
    for (int mt = 0; mt < 2; mt++)
        #pragma unroll
        for (int nt = 0; nt < 4; nt++)
            #pragma unroll
            for (int r = 0; r < 4; r++) { accg[mt][nt][r] = 0.f; accu[mt][nt][r] = 0.f; }

    // ---- prologue: load + store chunk 0 into stage 0 ----
    float4 ra0 = *(const float4*)(aptr[0]);
    float4 ra1 = *(const float4*)(aptr[1]);
    float4 rb0 = *(const float4*)(bp);
    float4 rb1 = *(const float4*)(bp + (size_t)8 * IDIM);
    {
        unsigned h0, l0, h1, l1;
        split2(ra0.x, ra0.y, h0, l0); split2(ra0.z, ra0.w, h1, l1);
        *(uint2*)&Ah[0][mA[0] * A_STR + kA[0]] = make_uint2(h0, h1);
        *(uint2*)&Al[0][mA[0] * A_STR + kA[0]] = make_uint2(l0, l1);
        split2(ra1.x, ra1.y, h0, l0); split2(ra1.z, ra1.w, h1, l1);
        *(uint2*)&Ah[0][mA[1] * A_STR + kA[1]] = make_uint2(h0, h1);
        *(uint2*)&Al[0][mA[1] * A_STR + kA[1]] = make_uint2(l0, l1);
        split2(rb0.x, rb0.y, h0, l0); split2(rb0.z, rb0.w, h1, l1);
        *(uint2*)&BH0[kr * B_STR + nq] = make_uint2(h0, h1);
        *(uint2*)&BL0[kr * B_STR + nq] = make_uint2(l0, l1);
        split2(rb1.x, rb1.y, h0, l0); split2(rb1.z, rb1.w, h1, l1);
        *(uint2*)&BH0[(kr + 8) * B_STR + nq] = make_uint2(h0, h1);
        *(uint2*)&BL0[(kr + 8) * B_STR + nq] = make_uint2(l0, l1);
    }
    __syncthreads();

    const int NCH = ND / 16;
    for (int c = 0; c < NCH; c++) {
        int p = c & 1;
        bool more = (c + 1 < NCH);
        // issue global prefetch for chunk c+1
        if (more) {
            int kt = (c + 1) * 16;
            ra0 = *(const float4*)(aptr[0] + kt);
            ra1 = *(const float4*)(aptr[1] + kt);
            rb0 = *(const float4*)(bp + (size_t)kt * IDIM);
            rb1 = *(const float4*)(bp + (size_t)(kt + 8) * IDIM);
        }
        // fragments + mma on stage p
        {
            uint32_t ao = p * A_SZB, bo = p * B_SZB;
            unsigned ah[2][4], al[2][4];
            ldsm4(ah[0], a_ld_h[0] + ao); ldsm4(ah[1], a_ld_h[1] + ao);
            ldsm4(al[0], a_ld_l[0] + ao); ldsm4(al[1], a_ld_l[1] + ao);
            #pragma unroll
            for (int np = 0; np < 2; np++) {
                unsigned bgh[4], bgl[4], buh[4], bul[4];
                ldsm4t(bgh, b_ld[0][np] + bo); ldsm4t(bgl, b_ld[1][np] + bo);
                ldsm4t(buh, b_ld[2][np] + bo); ldsm4t(bul, b_ld[3][np] + bo);
                #pragma unroll
                for (int j = 0; j < 2; j++) {
                    int nt = np * 2 + j;
                    #pragma unroll
                    for (int mt = 0; mt < 2; mt++) {
                        mma_bf16(accg[mt][nt], ah[mt], &bgh[2 * j]);
                        mma_bf16(accg[mt][nt], al[mt], &bgh[2 * j]);
                        mma_bf16(accg[mt][nt], ah[mt], &bgl[2 * j]);
                        mma_bf16(accu[mt][nt], ah[mt], &buh[2 * j]);
                        mma_bf16(accu[mt][nt], al[mt], &buh[2 * j]);
                        mma_bf16(accu[mt][nt], ah[mt], &bul[2 * j]);
                    }
                }
            }
        }
        // store chunk c+1 into stage p^1
        if (more) {
            int q = p ^ 1;
            unsigned short* BHq = mat ? Buh[q] : Bgh[q];
            unsigned short* BLq = mat ? Bul[q] : Bgl[q];
            unsigned h0, l0, h1, l1;
            split2(ra0.x, ra0.y, h0, l0); split2(ra0.z, ra0.w, h1, l1);
            *(uint2*)&Ah[q][mA[0] * A_STR + kA[0]] = make_uint2(h0, h1);
            *(uint2*)&Al[q][mA[0] * A_STR + kA[0]] = make_uint2(l0, l1);
            split2(ra1.x, ra1.y, h0, l0); split2(ra1.z, ra1.w, h1, l1);
            *(uint2*)&Ah[q][mA[1] * A_STR + kA[1]] = make_uint2(h0, h1);
            *(uint2*)&Al[q][mA[1] * A_STR + kA[1]] = make_uint2(l0, l1);
            split2(rb0.x, rb0.y, h0, l0); split2(rb0.z, rb0.w, h1, l1);
            *(uint2*)&BHq[kr * B_STR + nq] = make_uint2(h0, h1);
            *(uint2*)&BLq[kr * B_STR + nq] = make_uint2(l0, l1);
            split2(rb1.x, rb1.y, h0, l0); split2(rb1.z, rb1.w, h1, l1);
            *(uint2*)&BHq[(kr + 8) * B_STR + nq] = make_uint2(h0, h1);
            *(uint2*)&BLq[(kr + 8) * B_STR + nq] = make_uint2(l0, l1);
        }
        __syncthreads();
    }

    // epilogue: silu(gate) * up -> fp32 H
    #pragma unroll
    for (int mt = 0; mt < 2; mt++) {
        #pragma unroll
        for (int half = 0; half < 2; half++) {
            int r = m0 + warpM * 32 + mt * 16 + half * 8 + gq;
            if (r >= cnt) continue;
            float* hrow = H + (size_t)(off + r) * IDIM + n0 + warpN * 32;
            #pragma unroll
            for (int nt = 0; nt < 4; nt++) {
                float gv0 = accg[mt][nt][half * 2 + 0];
                float gv1 = accg[mt][nt][half * 2 + 1];
                float uv0 = accu[mt][nt][half * 2 + 0];
                float uv1 = accu[mt][nt][half * 2 + 1];
                float2 hv;
                hv.x = gv0 / (1.f + expf(-gv0)) * uv0;
                hv.y = gv1 / (1.f + expf(-gv1)) * uv1;
                *(float2*)&hrow[nt * 8 + 2 * tq] = hv;
            }
        }
    }
}

// ---------------- GEMM 2: out (+)= H @ Wd ----------------
template<int IDIM, bool ROUTED>
__global__ void __launch_bounds__(256, 2)
gemm_down(const float* __restrict__ Wd,
          float* __restrict__ out) {
    int e   = ROUTED ? blockIdx.z : 0;
    int cnt = ROUTED ? g_counts[e]  : NT;
    int off = ROUTED ? g_offsets[e] : 0;
    int m0  = blockIdx.x * 128;
    if (m0 >= cnt) return;
    int n0  = blockIdx.y * 64;
    const float* wd = Wd + (size_t)e * IDIM * ND;
    const float* Hsrc = ROUTED ? g_h : g_hs;

    __shared__ __align__(16) unsigned short Ah[2][A_SZ], Al[2][A_SZ];
    __shared__ __align__(16) unsigned short Bh[2][B_SZ], Bl[2][B_SZ];

    int tid  = threadIdx.x;
    int lane = tid & 31, wid = tid >> 5;
    int warpM = wid >> 1, warpN = wid & 1;
    int gq = lane >> 2, tq = lane & 3;

    const float* aptr[2]; int mA[2], kA[2];
    #pragma unroll
    for (int l = 0; l < 2; l++) {
        int idx = tid + l * 256;
        mA[l] = idx >> 2; kA[l] = (idx & 3) << 2;
        int m = m0 + mA[l];
        int hr = (m < cnt) ? (off + m) : off;
        aptr[l] = Hsrc + (size_t)hr * IDIM + kA[l];
    }
    int kr = tid >> 4, nq = (tid & 15) << 2;
    const float* bp = wd + (size_t)kr * ND + n0 + nq;

    int arow = lane & 15, acolb = (lane >> 4) << 4;
    uint32_t a_ld_h[2], a_ld_l[2];
    #pragma unroll
    for (int mt = 0; mt < 2; mt++) {
        int r = warpM * 32 + mt * 16 + arow;
        a_ld_h[mt] = sptr(Ah) + r * (A_STR * 2) + acolb;
        a_ld_l[mt] = sptr(Al) + r * (A_STR * 2) + acolb;
    }
    int bkr = lane & 15;
    int bcolb = (warpN * 32) * 2 + ((lane >> 4) << 4);
    uint32_t b_ld_h[2], b_ld_l[2];
    #pragma unroll
    for (int np = 0; np < 2; np++) {
        b_ld_h[np] = sptr(Bh) + bkr * (B_STR * 2) + bcolb + np * 32;
        b_ld_l[np] = sptr(Bl) + bkr * (B_STR * 2) + bcolb + np * 32;
    }

    float acc[2][4][4];
    #pragma unroll
    for (int mt = 0; mt < 2; mt++)
        #pragma unroll
        for (int nt = 0; nt < 4; nt++)
            #pragma unroll
            for (int r = 0; r < 4; r++) acc[mt][nt][r] = 0.f;

    float4 ra0 = *(const float4*)(aptr[0]);
    float4 ra1 = *(const float4*)(aptr[1]);
    float4 rb  = *(const float4*)(bp);
    {
        unsigned h0, l0, h1, l1;
        split2(ra0.x, ra0.y, h0, l0); split2(ra0.z, ra0.w, h1, l1);
        *(uint2*)&Ah[0][mA[0] * A_STR + kA[0]] = make_uint2(h0, h1);
        *(uint2*)&Al[0][mA[0] * A_STR + kA[0]] = make_uint2(l0, l1);
        split2(ra1.x, ra1.y, h0, l0); split2(ra1.z, ra1.w, h1, l1);
        *(uint2*)&Ah[0][mA[1] * A_STR + kA[1]] = make_uint2(h0, h1);
        *(uint2*)&Al[0][mA[1] * A_STR + kA[1]] = make_uint2(l0, l1);
        split2(rb.x, rb.y, h0, l0); split2(rb.z, rb.w, h1, l1);
        *(uint2*)&Bh[0][kr * B_STR + nq] = make_uint2(h0, h1);
        *(uint2*)&Bl[0][kr * B_STR + nq] = make_uint2(l0, l1);
    }
    __syncthreads();

    const int NCH = IDIM / 16;
    for (int c = 0; c < NCH; c++) {
        int p = c & 1;
        bool more = (c + 1 < NCH);
        if (more) {
            int kt = (c + 1) * 16;
            ra0 = *(const float4*)(aptr[0] + kt);
            ra1 = *(const float4*)(aptr[1] + kt);
            rb  = *(const float4*)(bp + (size_t)kt * ND);
        }
        {
            uint32_t ao = p * A_SZB, bo = p * B_SZB;
            unsigned ah[2][4], al[2][4];
            ldsm4(ah[0], a_ld_h[0] + ao); ldsm4(ah[1], a_ld_h[1] + ao);
            ldsm4(al[0], a_ld_l[0] + ao); ldsm4(al[1], a_ld_l[1] + ao);
            #pragma unroll
            for (int np = 0; np < 2; np++) {
                unsigned bh[4], bl[4];
                ldsm4t(bh, b_ld_h[np] + bo); ldsm4t(bl, b_ld_l[np] + bo);
                #pragma unroll
                for (int j = 0; j < 2; j++) {
                    int nt = np * 2 + j;
                    #pragma unroll
                    for (int mt = 0; mt < 2; mt++) {
                        mma_bf16(acc[mt][nt], ah[mt], &bh[2 * j]);
                        mma_bf16(acc[mt][nt], al[mt], &bh[2 * j]);
                        mma_bf16(acc[mt][nt], ah[mt], &bl[2 * j]);
                    }
                }
            }
        }
        if (more) {
            int q = p ^ 1;
            unsigned h0, l0, h1, l1;
            split2(ra0.x, ra0.y, h0, l0); split2(ra0.z, ra0.w, h1, l1);
            *(uint2*)&Ah[q][mA[0] * A_STR + kA[0]] = make_uint2(h0, h1);
            *(uint2*)&Al[q][mA[0] * A_STR + kA[0]] = make_uint2(l0, l1);
            split2(ra1.x, ra1.y, h0, l0); split2(ra1.z, ra1.w, h1, l1);
            *(uint2*)&Ah[q][mA[1] * A_STR + kA[1]] = make_uint2(h0, h1);
            *(uint2*)&Al[q][mA[1] * A_STR + kA[1]] = make_uint2(l0, l1);
            split2(rb.x, rb.y, h0, l0); split2(rb.z, rb.w, h1, l1);
            *(uint2*)&Bh[q][kr * B_STR + nq] = make_uint2(h0, h1);
            *(uint2*)&Bl[q][kr * B_STR + nq] = make_uint2(l0, l1);
        }
        __syncthreads();
    }

    // epilogue
    #pragma unroll
    for (int mt = 0; mt < 2; mt++) {
        #pragma unroll
        for (int half = 0; half < 2; half++) {
            int r = m0 + warpM * 32 + mt * 16 + half * 8 + gq;
            if (r >= cnt) continue;
            if (ROUTED) {
                int grow = off + r;
                int tok  = g_rowlist[grow];
                float w  = g_roww[grow] * 2.5f;
                float* op = out + (size_t)tok * ND + n0 + warpN * 32;
                #pragma unroll
                for (int nt = 0; nt < 4; nt++) {
                    atomicAdd(&op[nt * 8 + 2 * tq],     w * acc[mt][nt][half * 2 + 0]);
                    atomicAdd(&op[nt * 8 + 2 * tq + 1], w * acc[mt][nt][half * 2 + 1]);
                }
            } else {
                float* op = out + (size_t)r * ND + n0 + warpN * 32;
                #pragma unroll
                for (int nt = 0; nt < 4; nt++) {
                    float2 v;
                    v.x = acc[mt][nt][half * 2 + 0];
                    v.y = acc[mt][nt][half * 2 + 1];
                    *(float2*)&op[nt * 8 + 2 * tq] = v;
                }
            }
        }
    }
}

// ---------------- launch ----------------
extern "C" void kernel_launch(void* const* d_in, const int* in_sizes, int n_in,
                              void* d_out, int out_size) {
    const float* x       = (const float*)d_in[0];
    const float* gate_w  = (const float*)d_in[1];
    const float* gate_b  = (const float*)d_in[2];
    const float* w_gate  = (const float*)d_in[3];
    const float* w_up    = (const float*)d_in[4];
    const float* w_down  = (const float*)d_in[5];
    const float* sw_gate = (const float*)d_in[6];
    const float* sw_up   = (const float*)d_in[7];
    const float* sw_down = (const float*)d_in[8];
    float* out = (float*)d_out;

    zero_kernel   <<<1, 32>>>();
    gate_kernel   <<<NT, 256>>>(x, gate_w, gate_b);
    scan_kernel   <<<1, 32>>>();
    scatter_kernel<<<NA / 256, 256>>>();

    // shared expert gate/up
    gemm_gated<NSI, false><<<dim3(NT / 128, NSI / 64, 1), 256>>>(x, sw_gate, sw_up);
    // routed experts gate/up
    gemm_gated<NI,  true ><<<dim3(NT / 128, NI  / 64, NE), 256>>>(x, w_gate, w_up);
    // shared down-proj: plain stores initialize out
    gemm_down<NSI, false><<<dim3(NT / 128, ND / 64, 1), 256>>>(sw_down, out);
    // routed down-proj: weighted atomic accumulation
    gemm_down<NI,  true ><<<dim3(NT / 128, ND / 64, NE), 256>>>(w_down, out);
}